// round 6
// baseline (speedup 1.0000x reference)
#include <cuda_runtime.h>

#define N_NODES 50000
#define N_EDGES 300000
#define F_IN 11
#define D 256

// Scratch (bss, allowed per harness rules)
__device__ float g_dinv[N_NODES];            // deg -> deg^{-1/2} in place
__device__ float g_h0 [N_NODES * D];         // embed output
__device__ float g_hw [N_NODES * D];         // h @ W (per layer, reused)
__device__ float g_ag [N_NODES * D];         // layer-1 aggregated (pre-relu)

// ---------------- degree ----------------
__global__ void deg_init(float* deg, int n) {
    int i = blockIdx.x * blockDim.x + threadIdx.x;
    if (i < n) deg[i] = 1.0f;                 // self-loop
}
__global__ void deg_count(const int* __restrict__ dst, float* deg, int e) {
    int i = blockIdx.x * blockDim.x + threadIdx.x;
    if (i < e) atomicAdd(&deg[dst[i]], 1.0f);
}
__global__ void deg_rsqrt(float* deg, int n) {
    int i = blockIdx.x * blockDim.x + threadIdx.x;
    if (i < n) deg[i] = rsqrtf(deg[i]);       // deg >= 1 always (self-loop)
}

// ---------------- embed: h0 = relu(x @ We + be) ----------------
// 256 threads = one output column each; 8 nodes per block.
__global__ __launch_bounds__(256) void embed_kernel(
    const float* __restrict__ x, const float* __restrict__ W,
    const float* __restrict__ b, float* __restrict__ h0, int n)
{
    __shared__ float xs[8][F_IN];
    int j = threadIdx.x;
    int node0 = blockIdx.x * 8;
    // load 8 x-rows into smem
    int t = threadIdx.x;
    if (t < 8 * F_IN) {
        int nn = t / F_IN, kk = t % F_IN;
        int gi = node0 + nn;
        xs[nn][kk] = (gi < n) ? x[gi * F_IN + kk] : 0.0f;
    }
    __syncthreads();
    float wcol[F_IN];
#pragma unroll
    for (int k = 0; k < F_IN; k++) wcol[k] = W[k * D + j];
    float bj = b[j];
#pragma unroll
    for (int nn = 0; nn < 8; nn++) {
        int gi = node0 + nn;
        if (gi >= n) return;
        float s = bj;
#pragma unroll
        for (int k = 0; k < F_IN; k++) s = fmaf(xs[nn][k], wcol[k], s);
        h0[gi * D + j] = fmaxf(s, 0.0f);
    }
}

// ---------------- SGEMM: C[M,256] = A[M,256] @ B[256,256] ----------------
// BM=BN=64, BK=16, 256 threads, 4x4 microtile. Optional relu on A load.
template <bool RELU_A>
__global__ __launch_bounds__(256) void sgemm_k(
    const float* __restrict__ A, const float* __restrict__ B,
    float* __restrict__ C, int M)
{
    __shared__ float As[16][64];
    __shared__ float Bs[16][64];
    int t  = threadIdx.x;
    int m0 = blockIdx.y * 64;
    int n0 = blockIdx.x * 64;
    int tx = t & 15, ty = t >> 4;

    int arow = t >> 2;            // 0..63
    int ak   = (t & 3) * 4;       // 0,4,8,12
    int bcol = tx * 4;            // 0..60

    float acc[4][4];
#pragma unroll
    for (int i = 0; i < 4; i++)
#pragma unroll
        for (int j = 0; j < 4; j++) acc[i][j] = 0.0f;

    for (int k0 = 0; k0 < 256; k0 += 16) {
        float4 av = make_float4(0.f, 0.f, 0.f, 0.f);
        int gr = m0 + arow;
        if (gr < M) av = *(const float4*)(A + gr * 256 + k0 + ak);
        if (RELU_A) {
            av.x = fmaxf(av.x, 0.f); av.y = fmaxf(av.y, 0.f);
            av.z = fmaxf(av.z, 0.f); av.w = fmaxf(av.w, 0.f);
        }
        As[ak + 0][arow] = av.x; As[ak + 1][arow] = av.y;
        As[ak + 2][arow] = av.z; As[ak + 3][arow] = av.w;

        float4 bv = *(const float4*)(B + (k0 + ty) * 256 + n0 + bcol);
        *(float4*)&Bs[ty][bcol] = bv;

        __syncthreads();
#pragma unroll
        for (int k = 0; k < 16; k++) {
            float4 a = *(const float4*)&As[k][ty * 4];
            float4 b = *(const float4*)&Bs[k][tx * 4];
            acc[0][0] = fmaf(a.x, b.x, acc[0][0]);
            acc[0][1] = fmaf(a.x, b.y, acc[0][1]);
            acc[0][2] = fmaf(a.x, b.z, acc[0][2]);
            acc[0][3] = fmaf(a.x, b.w, acc[0][3]);
            acc[1][0] = fmaf(a.y, b.x, acc[1][0]);
            acc[1][1] = fmaf(a.y, b.y, acc[1][1]);
            acc[1][2] = fmaf(a.y, b.z, acc[1][2]);
            acc[1][3] = fmaf(a.y, b.w, acc[1][3]);
            acc[2][0] = fmaf(a.z, b.x, acc[2][0]);
            acc[2][1] = fmaf(a.z, b.y, acc[2][1]);
            acc[2][2] = fmaf(a.z, b.z, acc[2][2]);
            acc[2][3] = fmaf(a.z, b.w, acc[2][3]);
            acc[3][0] = fmaf(a.w, b.x, acc[3][0]);
            acc[3][1] = fmaf(a.w, b.y, acc[3][1]);
            acc[3][2] = fmaf(a.w, b.z, acc[3][2]);
            acc[3][3] = fmaf(a.w, b.w, acc[3][3]);
        }
        __syncthreads();
    }
#pragma unroll
    for (int i = 0; i < 4; i++) {
        int row = m0 + ty * 4 + i;
        if (row < M) {
            float4 v = make_float4(acc[i][0], acc[i][1], acc[i][2], acc[i][3]);
            *(float4*)(C + row * 256 + n0 + tx * 4) = v;
        }
    }
}

// ---------------- self-loop + bias init: out = hw * dinv^2 + b ----------------
__global__ void self_bias_kernel(const float* __restrict__ hw,
                                 const float* __restrict__ dinv,
                                 const float* __restrict__ b,
                                 float* __restrict__ out, int n)
{
    int v = blockIdx.x * blockDim.x + threadIdx.x;   // over n*64 float4s
    if (v >= n * 64) return;
    int i  = v >> 6;
    int j4 = v & 63;
    float s = dinv[i]; s = s * s;
    float4 h = ((const float4*)hw)[v];
    float4 bb = ((const float4*)b)[j4];
    float4 o;
    o.x = fmaf(h.x, s, bb.x);
    o.y = fmaf(h.y, s, bb.y);
    o.z = fmaf(h.z, s, bb.z);
    o.w = fmaf(h.w, s, bb.w);
    ((float4*)out)[v] = o;
}

// ---------------- edge scatter: out[dst] += hw[src] * dinv[src]*dinv[dst] ----
// 64 threads per edge, float4 gather, 4 scalar atomicAdds each.
__global__ void scatter_kernel(const float* __restrict__ hw,
                               const int* __restrict__ src,
                               const int* __restrict__ dst,
                               const float* __restrict__ dinv,
                               float* __restrict__ out, int e)
{
    long long t = (long long)blockIdx.x * blockDim.x + threadIdx.x;
    int ei   = (int)(t >> 6);
    int lane = (int)(t & 63);
    if (ei >= e) return;
    int s = src[ei];
    int d = dst[ei];
    float norm = dinv[s] * dinv[d];
    float4 v = ((const float4*)hw)[s * 64 + lane];
    float* o = out + (size_t)d * 256 + lane * 4;
    atomicAdd(o + 0, v.x * norm);
    atomicAdd(o + 1, v.y * norm);
    atomicAdd(o + 2, v.z * norm);
    atomicAdd(o + 3, v.w * norm);
}

// ---------------- launch ----------------
extern "C" void kernel_launch(void* const* d_in, const int* in_sizes, int n_in,
                              void* d_out, int out_size)
{
    const float* x  = (const float*)d_in[0];
    const int*   ei = (const int*)  d_in[1];
    const float* We = (const float*)d_in[2];
    const float* be = (const float*)d_in[3];
    const float* W1 = (const float*)d_in[4];
    const float* b1 = (const float*)d_in[5];
    const float* W2 = (const float*)d_in[6];
    const float* b2 = (const float*)d_in[7];
    float* out = (float*)d_out;

    const int N = in_sizes[0] / F_IN;       // 50000
    const int E = in_sizes[1] / 2;          // 300000
    const int* src = ei;
    const int* dst = ei + E;

    float* dinv = nullptr; cudaGetSymbolAddress((void**)&dinv, g_dinv);
    float* h0   = nullptr; cudaGetSymbolAddress((void**)&h0,   g_h0);
    float* hw   = nullptr; cudaGetSymbolAddress((void**)&hw,   g_hw);
    float* ag   = nullptr; cudaGetSymbolAddress((void**)&ag,   g_ag);

    // degree / normalization
    deg_init <<<(N + 255) / 256, 256>>>(dinv, N);
    deg_count<<<(E + 255) / 256, 256>>>(dst, dinv, E);
    deg_rsqrt<<<(N + 255) / 256, 256>>>(dinv, N);

    // embed + relu
    embed_kernel<<<(N + 7) / 8, 256>>>(x, We, be, h0, N);

    dim3 gg(4, (N + 63) / 64);

    // layer 1: hw = h0 @ W1 ; ag = hw*dinv^2 + b1 ; scatter edges into ag
    sgemm_k<false><<<gg, 256>>>(h0, W1, hw, N);
    self_bias_kernel<<<(N * 64 + 255) / 256, 256>>>(hw, dinv, b1, ag, N);
    scatter_kernel<<<((long long)E * 64 + 255) / 256, 256>>>(hw, src, dst, dinv, ag, E);

    // layer 2: hw = relu(ag) @ W2 ; out = hw*dinv^2 + b2 ; scatter edges into out
    sgemm_k<true><<<gg, 256>>>(ag, W2, hw, N);
    self_bias_kernel<<<(N * 64 + 255) / 256, 256>>>(hw, dinv, b2, out, N);
    scatter_kernel<<<((long long)E * 64 + 255) / 256, 256>>>(hw, src, dst, dinv, out, E);
}

// round 9
// speedup vs baseline: 2.4213x; 2.4213x over previous
#include <cuda_runtime.h>

#define N_NODES 50000
#define N_EDGES 300000
#define F_IN 11
#define D 256

// Scratch (bss globals, allowed per harness rules)
__device__ float g_dinv[N_NODES];
__device__ float g_h0 [N_NODES * D];
__device__ float g_hw [N_NODES * D];
__device__ float g_ag [N_NODES * D];

// ---------------- degree ----------------
__global__ void deg_init(float* deg, int n) {
    int i = blockIdx.x * blockDim.x + threadIdx.x;
    if (i < n) deg[i] = 1.0f;                 // self-loop
}
__global__ void deg_count(const int* __restrict__ dst, float* deg, int e) {
    int i = blockIdx.x * blockDim.x + threadIdx.x;
    if (i < e) atomicAdd(&deg[dst[i]], 1.0f);
}
__global__ void deg_rsqrt(float* deg, int n) {
    int i = blockIdx.x * blockDim.x + threadIdx.x;
    if (i < n) deg[i] = rsqrtf(deg[i]);       // deg >= 1 always
}

// ---------------- embed: h0 = relu(x @ We + be) ----------------
__global__ __launch_bounds__(256) void embed_kernel(
    const float* __restrict__ x, const float* __restrict__ W,
    const float* __restrict__ b, float* __restrict__ h0, int n)
{
    __shared__ float xs[8][F_IN];
    int j = threadIdx.x;
    int node0 = blockIdx.x * 8;
    int t = threadIdx.x;
    if (t < 8 * F_IN) {
        int nn = t / F_IN, kk = t % F_IN;
        int gi = node0 + nn;
        xs[nn][kk] = (gi < n) ? x[gi * F_IN + kk] : 0.0f;
    }
    __syncthreads();
    float wcol[F_IN];
#pragma unroll
    for (int k = 0; k < F_IN; k++) wcol[k] = W[k * D + j];
    float bj = b[j];
#pragma unroll
    for (int nn = 0; nn < 8; nn++) {
        int gi = node0 + nn;
        if (gi >= n) return;
        float s = bj;
#pragma unroll
        for (int k = 0; k < F_IN; k++) s = fmaf(xs[nn][k], wcol[k], s);
        h0[gi * D + j] = fmaxf(s, 0.0f);
    }
}

// ---------------- SGEMM + fused self-loop/bias epilogue ----------------
// C_hw[M,256] = act(A)[M,256] @ B[256,256]
// C_ag[M,256] = C_hw * dinv[row]^2 + bias           (self-loop term + bias)
// BM=128, BN=64, BK=16, 256 threads, 8x4 microtile, double-buffered smem.
template <bool RELU_A>
__global__ __launch_bounds__(256) void sgemm_fused(
    const float* __restrict__ A, const float* __restrict__ B,
    const float* __restrict__ bias, const float* __restrict__ dinv,
    float* __restrict__ Chw, float* __restrict__ Cag, int M)
{
    __shared__ float As[2][16][132];   // [stage][k][m], padded
    __shared__ float Bs[2][16][64];    // [stage][k][n]

    const int t  = threadIdx.x;
    const int m0 = blockIdx.y * 128;
    const int n0 = blockIdx.x * 64;
    const int tx = t & 15;             // 0..15 -> 4 cols each
    const int ty = t >> 4;             // 0..15 -> 8 rows each

    // A load mapping: 128 rows x 16 k / 256 thr = 8 floats/thread
    const int arow = t >> 1;           // 0..127
    const int ak   = (t & 1) * 8;      // 0 or 8
    // B load mapping: 16 rows x 64 cols / 256 thr = 4 floats/thread
    const int brow = t >> 4;           // 0..15
    const int bcol = (t & 15) * 4;     // 0..60

    const int agr = m0 + arow;
    const bool avalid = (agr < M);
    const float* Aptr = A + (size_t)agr * 256 + ak;
    const float* Bptr = B + (size_t)brow * 256 + n0 + bcol;

    float acc[8][4];
#pragma unroll
    for (int i = 0; i < 8; i++)
#pragma unroll
        for (int j = 0; j < 4; j++) acc[i][j] = 0.0f;

    // ---- prologue: load tile 0 into stage 0 ----
    {
        float4 a0 = make_float4(0.f,0.f,0.f,0.f), a1 = a0;
        if (avalid) {
            a0 = *(const float4*)(Aptr);
            a1 = *(const float4*)(Aptr + 4);
        }
        if (RELU_A) {
            a0.x=fmaxf(a0.x,0.f); a0.y=fmaxf(a0.y,0.f); a0.z=fmaxf(a0.z,0.f); a0.w=fmaxf(a0.w,0.f);
            a1.x=fmaxf(a1.x,0.f); a1.y=fmaxf(a1.y,0.f); a1.z=fmaxf(a1.z,0.f); a1.w=fmaxf(a1.w,0.f);
        }
        As[0][ak+0][arow]=a0.x; As[0][ak+1][arow]=a0.y; As[0][ak+2][arow]=a0.z; As[0][ak+3][arow]=a0.w;
        As[0][ak+4][arow]=a1.x; As[0][ak+5][arow]=a1.y; As[0][ak+6][arow]=a1.z; As[0][ak+7][arow]=a1.w;
        *(float4*)&Bs[0][brow][bcol] = *(const float4*)(Bptr);
    }
    __syncthreads();

#pragma unroll 1
    for (int kt = 0; kt < 16; kt++) {
        const int cur = kt & 1;
        const int nxt = cur ^ 1;
        // issue next tile loads (overlap with compute via scoreboard)
        if (kt < 15) {
            const int k0 = (kt + 1) * 16;
            float4 a0 = make_float4(0.f,0.f,0.f,0.f), a1 = a0;
            if (avalid) {
                a0 = *(const float4*)(Aptr + k0);
                a1 = *(const float4*)(Aptr + k0 + 4);
            }
            float4 bv = *(const float4*)(Bptr + (size_t)k0 * 256);
            if (RELU_A) {
                a0.x=fmaxf(a0.x,0.f); a0.y=fmaxf(a0.y,0.f); a0.z=fmaxf(a0.z,0.f); a0.w=fmaxf(a0.w,0.f);
                a1.x=fmaxf(a1.x,0.f); a1.y=fmaxf(a1.y,0.f); a1.z=fmaxf(a1.z,0.f); a1.w=fmaxf(a1.w,0.f);
            }
            As[nxt][ak+0][arow]=a0.x; As[nxt][ak+1][arow]=a0.y; As[nxt][ak+2][arow]=a0.z; As[nxt][ak+3][arow]=a0.w;
            As[nxt][ak+4][arow]=a1.x; As[nxt][ak+5][arow]=a1.y; As[nxt][ak+6][arow]=a1.z; As[nxt][ak+7][arow]=a1.w;
            *(float4*)&Bs[nxt][brow][bcol] = bv;
        }
        // compute on current stage
#pragma unroll
        for (int k = 0; k < 16; k++) {
            float4 a0 = *(const float4*)&As[cur][k][ty * 8];
            float4 a1 = *(const float4*)&As[cur][k][ty * 8 + 4];
            float4 bv = *(const float4*)&Bs[cur][k][tx * 4];
            float ar[8] = {a0.x,a0.y,a0.z,a0.w,a1.x,a1.y,a1.z,a1.w};
            float br[4] = {bv.x,bv.y,bv.z,bv.w};
#pragma unroll
            for (int i = 0; i < 8; i++)
#pragma unroll
                for (int j = 0; j < 4; j++)
                    acc[i][j] = fmaf(ar[i], br[j], acc[i][j]);
        }
        __syncthreads();
    }

    // ---- epilogue: write hw and ag = hw*dinv^2 + bias ----
    float4 bb = *(const float4*)(bias + n0 + tx * 4);
#pragma unroll
    for (int i = 0; i < 8; i++) {
        int row = m0 + ty * 8 + i;
        if (row < M) {
            float4 v = make_float4(acc[i][0], acc[i][1], acc[i][2], acc[i][3]);
            size_t off = (size_t)row * 256 + n0 + tx * 4;
            *(float4*)(Chw + off) = v;
            float s = dinv[row]; s = s * s;
            float4 o;
            o.x = fmaf(v.x, s, bb.x);
            o.y = fmaf(v.y, s, bb.y);
            o.z = fmaf(v.z, s, bb.z);
            o.w = fmaf(v.w, s, bb.w);
            *(float4*)(Cag + off) = o;
        }
    }
}

// ---------------- edge scatter: out[dst] += hw[src] * dinv[src]*dinv[dst] ----
// 64 threads per edge, one float4 gather + one red.global.add.v4.f32 each.
__global__ void scatter_kernel(const float* __restrict__ hw,
                               const int* __restrict__ src,
                               const int* __restrict__ dst,
                               const float* __restrict__ dinv,
                               float* __restrict__ out, int e)
{
    long long t = (long long)blockIdx.x * blockDim.x + threadIdx.x;
    int ei   = (int)(t >> 6);
    int lane = (int)(t & 63);
    if (ei >= e) return;
    int s = src[ei];
    int d = dst[ei];
    float norm = dinv[s] * dinv[d];
    float4 v = ((const float4*)hw)[s * 64 + lane];
    float* o = out + (size_t)d * 256 + lane * 4;
    asm volatile("red.global.add.v4.f32 [%0], {%1,%2,%3,%4};"
                 :: "l"(o), "f"(v.x * norm), "f"(v.y * norm),
                    "f"(v.z * norm), "f"(v.w * norm)
                 : "memory");
}

// ---------------- launch ----------------
extern "C" void kernel_launch(void* const* d_in, const int* in_sizes, int n_in,
                              void* d_out, int out_size)
{
    const float* x  = (const float*)d_in[0];
    const int*   ei = (const int*)  d_in[1];
    const float* We = (const float*)d_in[2];
    const float* be = (const float*)d_in[3];
    const float* W1 = (const float*)d_in[4];
    const float* b1 = (const float*)d_in[5];
    const float* W2 = (const float*)d_in[6];
    const float* b2 = (const float*)d_in[7];
    float* out = (float*)d_out;

    const int N = in_sizes[0] / F_IN;       // 50000
    const int E = in_sizes[1] / 2;          // 300000
    const int* src = ei;
    const int* dst = ei + E;

    float* dinv = nullptr; cudaGetSymbolAddress((void**)&dinv, g_dinv);
    float* h0   = nullptr; cudaGetSymbolAddress((void**)&h0,   g_h0);
    float* hw   = nullptr; cudaGetSymbolAddress((void**)&hw,   g_hw);
    float* ag   = nullptr; cudaGetSymbolAddress((void**)&ag,   g_ag);

    // degree / normalization
    deg_init <<<(N + 255) / 256, 256>>>(dinv, N);
    deg_count<<<(E + 255) / 256, 256>>>(dst, dinv, E);
    deg_rsqrt<<<(N + 255) / 256, 256>>>(dinv, N);

    // embed + relu
    embed_kernel<<<(N + 7) / 8, 256>>>(x, We, be, h0, N);

    dim3 gg(256 / 64, (N + 127) / 128);     // (4, 391)

    // layer 1: hw = h0 @ W1 ; ag = hw*dinv^2 + b1 (fused) ; scatter edges into ag
    sgemm_fused<false><<<gg, 256>>>(h0, W1, b1, dinv, hw, ag, N);
    scatter_kernel<<<((long long)E * 64 + 255) / 256, 256>>>(hw, src, dst, dinv, ag, E);

    // layer 2: hw = relu(ag) @ W2 ; out = hw*dinv^2 + b2 (fused) ; scatter into out
    sgemm_fused<true><<<gg, 256>>>(ag, W2, b2, dinv, hw, out, N);
    scatter_kernel<<<((long long)E * 64 + 255) / 256, 256>>>(hw, src, dst, dinv, out, E);
}

// round 11
// speedup vs baseline: 3.1437x; 1.2984x over previous
#include <cuda_runtime.h>
#include <cstdint>

#define N_NODES 50000
#define N_EDGES 300000
#define F_IN 11
#define D 256

// Scratch (bss globals, allowed per harness rules)
__device__ float g_dinv[N_NODES];
__device__ float g_h0 [N_NODES * D];
__device__ float g_hw [N_NODES * D];
__device__ float g_ag [N_NODES * D];

// ======================= helpers =======================
__device__ __forceinline__ uint32_t smem_u32(const void* p) {
    uint32_t a;
    asm("{ .reg .u64 t; cvta.to.shared.u64 t, %1; cvt.u32.u64 %0, t; }" : "=r"(a) : "l"(p));
    return a;
}

// split (v0,v1) into packed bf16x2 hi + bf16x2 residual lo (lane0 = low half)
__device__ __forceinline__ void split2(float v0, float v1, uint32_t& hi, uint32_t& lo) {
    uint32_t h;
    asm("cvt.rn.bf16x2.f32 %0, %1, %2;" : "=r"(h) : "f"(v1), "f"(v0));
    float r0 = v0 - __uint_as_float(h << 16);
    float r1 = v1 - __uint_as_float(h & 0xFFFF0000u);
    uint32_t l;
    asm("cvt.rn.bf16x2.f32 %0, %1, %2;" : "=r"(l) : "f"(r1), "f"(r0));
    hi = h; lo = l;
}

__device__ __forceinline__ void ldm_x4(uint32_t* r, uint32_t addr) {
    asm volatile("ldmatrix.sync.aligned.m8n8.x4.shared.b16 {%0,%1,%2,%3}, [%4];"
                 : "=r"(r[0]), "=r"(r[1]), "=r"(r[2]), "=r"(r[3]) : "r"(addr));
}
__device__ __forceinline__ void ldm_x2(uint32_t* r, uint32_t addr) {
    asm volatile("ldmatrix.sync.aligned.m8n8.x2.shared.b16 {%0,%1}, [%2];"
                 : "=r"(r[0]), "=r"(r[1]) : "r"(addr));
}
__device__ __forceinline__ void mma_bf16(float* c, const uint32_t* a, const uint32_t* b) {
    asm volatile("mma.sync.aligned.m16n8k16.row.col.f32.bf16.bf16.f32 "
                 "{%0,%1,%2,%3}, {%4,%5,%6,%7}, {%8,%9}, {%0,%1,%2,%3};"
                 : "+f"(c[0]), "+f"(c[1]), "+f"(c[2]), "+f"(c[3])
                 : "r"(a[0]), "r"(a[1]), "r"(a[2]), "r"(a[3]), "r"(b[0]), "r"(b[1]));
}

// ======================= small kernels =======================
__global__ void deg_init(float* deg, int n) {
    int i = blockIdx.x * blockDim.x + threadIdx.x;
    if (i < n) deg[i] = 1.0f;                 // self-loop
}
__global__ void deg_count(const int* __restrict__ dst, float* deg, int e) {
    int i = blockIdx.x * blockDim.x + threadIdx.x;
    if (i < e) atomicAdd(&deg[dst[i]], 1.0f);
}
__global__ void deg_rsqrt(float* deg, int n) {
    int i = blockIdx.x * blockDim.x + threadIdx.x;
    if (i < n) deg[i] = rsqrtf(deg[i]);       // deg >= 1 always
}

__global__ __launch_bounds__(256) void embed_kernel(
    const float* __restrict__ x, const float* __restrict__ W,
    const float* __restrict__ b, float* __restrict__ h0, int n)
{
    __shared__ float xs[8][F_IN];
    int j = threadIdx.x;
    int node0 = blockIdx.x * 8;
    int t = threadIdx.x;
    if (t < 8 * F_IN) {
        int nn = t / F_IN, kk = t % F_IN;
        int gi = node0 + nn;
        xs[nn][kk] = (gi < n) ? x[gi * F_IN + kk] : 0.0f;
    }
    __syncthreads();
    float wcol[F_IN];
#pragma unroll
    for (int k = 0; k < F_IN; k++) wcol[k] = W[k * D + j];
    float bj = b[j];
#pragma unroll
    for (int nn = 0; nn < 8; nn++) {
        int gi = node0 + nn;
        if (gi >= n) return;
        float s = bj;
#pragma unroll
        for (int k = 0; k < F_IN; k++) s = fmaf(xs[nn][k], wcol[k], s);
        h0[gi * D + j] = fmaxf(s, 0.0f);
    }
}

// ======================= bf16-split tensor-core GEMM =======================
// Chw[M,256] = act(A)[M,256] @ W[256,256];  Cag = Chw*dinv[row]^2 + bias
// BM=128, BN=64, BK=32. 8 warps, each 32x32 out via m16n8k16 (2m x 4n frags).
// 3-term bf16 emulation: Ah*Bh + Ah*Bl + Al*Bh, fp32 accumulate.
#define BM 128
#define BN 64
#define BK 32
#define SA 40    // padded bf16 row stride (80B: conflict-free ldmatrix phases)

template <bool RELU_A>
__global__ __launch_bounds__(256, 2) void gemm_mma(
    const float* __restrict__ A, const float* __restrict__ W,
    const float* __restrict__ bias, const float* __restrict__ dinv,
    float* __restrict__ Chw, float* __restrict__ Cag, int M)
{
    __shared__ __align__(16) uint16_t Ahi[BM * SA];
    __shared__ __align__(16) uint16_t Alo[BM * SA];
    __shared__ __align__(16) uint16_t Bhi[BN * SA];
    __shared__ __align__(16) uint16_t Blo[BN * SA];
    __shared__ __align__(16) float    stg[BK * BN];   // fp32 staging [k][n]

    const int t   = threadIdx.x;
    const int wid = t >> 5, lid = t & 31;
    const int m0  = blockIdx.y * BM;
    const int n0  = blockIdx.x * BN;
    const int wm  = wid & 3;          // 4 warp-rows of 32
    const int wn  = wid >> 2;         // 2 warp-cols of 32

    const uint32_t sAhi = smem_u32(Ahi), sAlo = smem_u32(Alo);
    const uint32_t sBhi = smem_u32(Bhi), sBlo = smem_u32(Blo);

    float acc[2][4][4];
#pragma unroll
    for (int i = 0; i < 2; i++)
#pragma unroll
        for (int j = 0; j < 4; j++)
#pragma unroll
            for (int k = 0; k < 4; k++) acc[i][j][k] = 0.0f;

    // precomputed ldmatrix lane addressing offsets
    const int a_r16 = lid & 15, a_kh = lid >> 4;       // x4: row, k-half
    const int b_n8  = lid & 7,  b_kh = (lid >> 3) & 1; // x2: n-row, k-half

#pragma unroll 1
    for (int st = 0; st < 256 / BK; st++) {
        const int kc = st * BK;

        // ---- A: load 128x32 fp32 (coalesced), split, store swizz-free padded ----
#pragma unroll
        for (int tt = t; tt < BM * 4; tt += 256) {
            int row = tt >> 2, kg = tt & 3;
            float4 a0 = make_float4(0.f, 0.f, 0.f, 0.f), a1 = a0;
            int gr = m0 + row;
            if (gr < M) {
                const float* p = A + (size_t)gr * 256 + kc + kg * 8;
                a0 = *(const float4*)p;
                a1 = *(const float4*)(p + 4);
            }
            if (RELU_A) {
                a0.x = fmaxf(a0.x, 0.f); a0.y = fmaxf(a0.y, 0.f);
                a0.z = fmaxf(a0.z, 0.f); a0.w = fmaxf(a0.w, 0.f);
                a1.x = fmaxf(a1.x, 0.f); a1.y = fmaxf(a1.y, 0.f);
                a1.z = fmaxf(a1.z, 0.f); a1.w = fmaxf(a1.w, 0.f);
            }
            uint4 h4, l4;
            split2(a0.x, a0.y, h4.x, l4.x);
            split2(a0.z, a0.w, h4.y, l4.y);
            split2(a1.x, a1.y, h4.z, l4.z);
            split2(a1.z, a1.w, h4.w, l4.w);
            uint32_t off = (uint32_t)(row * SA + kg * 8) * 2;
            *(uint4*)((char*)Ahi + off) = h4;
            *(uint4*)((char*)Alo + off) = l4;
        }

        // ---- W stage: rows kc..kc+31, cols n0..n0+63 (coalesced float4) ----
#pragma unroll
        for (int tt = t; tt < BK * (BN / 4); tt += 256) {
            int k = tt >> 4, nf = (tt & 15) * 4;
            float4 v = *(const float4*)(W + (size_t)(kc + k) * 256 + n0 + nf);
            *(float4*)&stg[k * BN + nf] = v;
        }
        __syncthreads();

        // ---- B transpose+convert: Bsm[n][k] = W[kc+k][n0+n] ----
        {
            int kg = t >> 6, n = t & 63;          // 256 tasks, 1/thread
            float v[8];
#pragma unroll
            for (int j = 0; j < 8; j++) v[j] = stg[(kg * 8 + j) * BN + n];
            uint4 h4, l4;
            split2(v[0], v[1], h4.x, l4.x);
            split2(v[2], v[3], h4.y, l4.y);
            split2(v[4], v[5], h4.z, l4.z);
            split2(v[6], v[7], h4.w, l4.w);
            uint32_t off = (uint32_t)(n * SA + kg * 8) * 2;
            *(uint4*)((char*)Bhi + off) = h4;
            *(uint4*)((char*)Blo + off) = l4;
        }
        __syncthreads();

        // ---- compute: 2 k16 slices x (2m x 4n) x 3 terms ----
#pragma unroll
        for (int ks = 0; ks < 2; ks++) {
            const int kb = ks * 16;
            uint32_t ah[2][4], al[2][4];
#pragma unroll
            for (int mt = 0; mt < 2; mt++) {
                uint32_t off = (uint32_t)((wm * 32 + mt * 16 + a_r16) * SA + kb + a_kh * 8) * 2;
                ldm_x4(ah[mt], sAhi + off);
                ldm_x4(al[mt], sAlo + off);
            }
            uint32_t bh[4][2], bl[4][2];
#pragma unroll
            for (int nt = 0; nt < 4; nt++) {
                uint32_t off = (uint32_t)((wn * 32 + nt * 8 + b_n8) * SA + kb + b_kh * 8) * 2;
                ldm_x2(bh[nt], sBhi + off);
                ldm_x2(bl[nt], sBlo + off);
            }
#pragma unroll
            for (int mt = 0; mt < 2; mt++)
#pragma unroll
                for (int nt = 0; nt < 4; nt++) {
                    mma_bf16(acc[mt][nt], ah[mt], bh[nt]);
                    mma_bf16(acc[mt][nt], ah[mt], bl[nt]);
                    mma_bf16(acc[mt][nt], al[mt], bh[nt]);
                }
        }
        __syncthreads();
    }

    // ---- epilogue: write hw and ag = hw*dinv^2 + bias ----
    const int rbase = m0 + wm * 32 + (lid >> 2);
    const int cbase = n0 + wn * 32 + (lid & 3) * 2;
#pragma unroll
    for (int nt = 0; nt < 4; nt++) {
        const int col = cbase + nt * 8;
        float2 bb = make_float2(bias[col], bias[col + 1]);
#pragma unroll
        for (int mt = 0; mt < 2; mt++) {
#pragma unroll
            for (int h = 0; h < 2; h++) {       // row, row+8
                int row = rbase + mt * 16 + h * 8;
                if (row < M) {
                    float vx = acc[mt][nt][2 * h + 0];
                    float vy = acc[mt][nt][2 * h + 1];
                    size_t off = (size_t)row * 256 + col;
                    *(float2*)(Chw + off) = make_float2(vx, vy);
                    float s = dinv[row]; s = s * s;
                    *(float2*)(Cag + off) =
                        make_float2(fmaf(vx, s, bb.x), fmaf(vy, s, bb.y));
                }
            }
        }
    }
}

// ======================= edge scatter =======================
__global__ void scatter_kernel(const float* __restrict__ hw,
                               const int* __restrict__ src,
                               const int* __restrict__ dst,
                               const float* __restrict__ dinv,
                               float* __restrict__ out, int e)
{
    long long t = (long long)blockIdx.x * blockDim.x + threadIdx.x;
    int ei   = (int)(t >> 6);
    int lane = (int)(t & 63);
    if (ei >= e) return;
    int s = src[ei];
    int d = dst[ei];
    float norm = dinv[s] * dinv[d];
    float4 v = ((const float4*)hw)[s * 64 + lane];
    float* o = out + (size_t)d * 256 + lane * 4;
    asm volatile("red.global.add.v4.f32 [%0], {%1,%2,%3,%4};"
                 :: "l"(o), "f"(v.x * norm), "f"(v.y * norm),
                    "f"(v.z * norm), "f"(v.w * norm)
                 : "memory");
}

// ======================= launch =======================
extern "C" void kernel_launch(void* const* d_in, const int* in_sizes, int n_in,
                              void* d_out, int out_size)
{
    const float* x  = (const float*)d_in[0];
    const int*   ei = (const int*)  d_in[1];
    const float* We = (const float*)d_in[2];
    const float* be = (const float*)d_in[3];
    const float* W1 = (const float*)d_in[4];
    const float* b1 = (const float*)d_in[5];
    const float* W2 = (const float*)d_in[6];
    const float* b2 = (const float*)d_in[7];
    float* out = (float*)d_out;

    const int N = in_sizes[0] / F_IN;       // 50000
    const int E = in_sizes[1] / 2;          // 300000
    const int* src = ei;
    const int* dst = ei + E;

    float* dinv = nullptr; cudaGetSymbolAddress((void**)&dinv, g_dinv);
    float* h0   = nullptr; cudaGetSymbolAddress((void**)&h0,   g_h0);
    float* hw   = nullptr; cudaGetSymbolAddress((void**)&hw,   g_hw);
    float* ag   = nullptr; cudaGetSymbolAddress((void**)&ag,   g_ag);

    // degree / normalization
    deg_init <<<(N + 255) / 256, 256>>>(dinv, N);
    deg_count<<<(E + 255) / 256, 256>>>(dst, dinv, E);
    deg_rsqrt<<<(N + 255) / 256, 256>>>(dinv, N);

    // embed + relu
    embed_kernel<<<(N + 7) / 8, 256>>>(x, We, be, h0, N);

    dim3 gg(D / BN, (N + BM - 1) / BM);     // (4, 391)

    // layer 1: hw = h0 @ W1 ; ag = hw*dinv^2 + b1 (fused) ; scatter into ag
    gemm_mma<false><<<gg, 256>>>(h0, W1, b1, dinv, hw, ag, N);
    scatter_kernel<<<((long long)E * 64 + 255) / 256, 256>>>(hw, src, dst, dinv, ag, E);

    // layer 2: hw = relu(ag) @ W2 ; out = hw*dinv^2 + b2 (fused) ; scatter into out
    gemm_mma<true><<<gg, 256>>>(ag, W2, b2, dinv, hw, out, N);
    scatter_kernel<<<((long long)E * 64 + 255) / 256, 256>>>(hw, src, dst, dinv, out, E);
}

// round 13
// speedup vs baseline: 3.4642x; 1.1019x over previous
#include <cuda_runtime.h>
#include <cuda_bf16.h>
#include <cstdint>

#define N_NODES 50000
#define N_EDGES 300000
#define F_IN 11
#define D 256

// Scratch (bss globals, allowed per harness rules)
__device__ float g_dinv[N_NODES];
__device__ float g_hw [N_NODES * D];
__device__ float g_ag [N_NODES * D];
// split bf16 activation buffers (reused: h0 for layer1, relu(ag) for layer2)
__device__ __nv_bfloat16 g_ahi[N_NODES * D];
__device__ __nv_bfloat16 g_alo[N_NODES * D];
// split, transposed weights: Wt[n][k] = W[k][n]
__device__ __nv_bfloat16 g_w1hi[D * D], g_w1lo[D * D];
__device__ __nv_bfloat16 g_w2hi[D * D], g_w2lo[D * D];

// ======================= helpers =======================
__device__ __forceinline__ uint32_t smem_u32(const void* p) {
    uint32_t a;
    asm("{ .reg .u64 t; cvta.to.shared.u64 t, %1; cvt.u32.u64 %0, t; }" : "=r"(a) : "l"(p));
    return a;
}
// split (v0,v1) into packed bf16x2 hi + bf16x2 residual lo (lane0 = low half)
__device__ __forceinline__ void split2(float v0, float v1, uint32_t& hi, uint32_t& lo) {
    uint32_t h;
    asm("cvt.rn.bf16x2.f32 %0, %1, %2;" : "=r"(h) : "f"(v1), "f"(v0));
    float r0 = v0 - __uint_as_float(h << 16);
    float r1 = v1 - __uint_as_float(h & 0xFFFF0000u);
    uint32_t l;
    asm("cvt.rn.bf16x2.f32 %0, %1, %2;" : "=r"(l) : "f"(r1), "f"(r0));
    hi = h; lo = l;
}
__device__ __forceinline__ void ldm_x4(uint32_t* r, uint32_t addr) {
    asm volatile("ldmatrix.sync.aligned.m8n8.x4.shared.b16 {%0,%1,%2,%3}, [%4];"
                 : "=r"(r[0]), "=r"(r[1]), "=r"(r[2]), "=r"(r[3]) : "r"(addr));
}
__device__ __forceinline__ void ldm_x2(uint32_t* r, uint32_t addr) {
    asm volatile("ldmatrix.sync.aligned.m8n8.x2.shared.b16 {%0,%1}, [%2];"
                 : "=r"(r[0]), "=r"(r[1]) : "r"(addr));
}
__device__ __forceinline__ void mma_bf16(float* c, const uint32_t* a, const uint32_t* b) {
    asm volatile("mma.sync.aligned.m16n8k16.row.col.f32.bf16.bf16.f32 "
                 "{%0,%1,%2,%3}, {%4,%5,%6,%7}, {%8,%9}, {%0,%1,%2,%3};"
                 : "+f"(c[0]), "+f"(c[1]), "+f"(c[2]), "+f"(c[3])
                 : "r"(a[0]), "r"(a[1]), "r"(a[2]), "r"(a[3]), "r"(b[0]), "r"(b[1]));
}
__device__ __forceinline__ void cp16(uint32_t dst, const __nv_bfloat16* src, uint32_t sz) {
    uint64_t g;
    asm("cvta.to.global.u64 %0, %1;" : "=l"(g) : "l"(src));
    asm volatile("cp.async.cg.shared.global [%0], [%1], 16, %2;"
                 :: "r"(dst), "l"(g), "r"(sz) : "memory");
}
#define CP_COMMIT() asm volatile("cp.async.commit_group;" ::: "memory")
#define CP_WAIT(n)  asm volatile("cp.async.wait_group %0;" :: "n"(n) : "memory")

// ======================= small kernels =======================
__global__ void deg_init(float* deg, int n) {
    int i = blockIdx.x * blockDim.x + threadIdx.x;
    if (i < n) deg[i] = 1.0f;                 // self-loop
}
__global__ void deg_count(const int* __restrict__ dst, float* deg, int e) {
    int i = blockIdx.x * blockDim.x + threadIdx.x;
    if (i < e) atomicAdd(&deg[dst[i]], 1.0f);
}
__global__ void deg_rsqrt(float* deg, int n) {
    int i = blockIdx.x * blockDim.x + threadIdx.x;
    if (i < n) deg[i] = rsqrtf(deg[i]);       // deg >= 1 always
}

// W[k][n] -> Wt_hi[n][k], Wt_lo[n][k] (bf16 split, one-time)
__global__ __launch_bounds__(256) void wt_split(
    const float* __restrict__ W,
    __nv_bfloat16* __restrict__ Whi, __nv_bfloat16* __restrict__ Wlo)
{
    int idx = blockIdx.x * 256 + threadIdx.x;   // 65536 total
    int k = idx >> 8, n = idx & 255;
    float v = W[k * 256 + n];                   // coalesced read
    __nv_bfloat16 h = __float2bfloat16(v);
    float r = v - __bfloat162float(h);
    Whi[n * 256 + k] = h;                       // transposed write
    Wlo[n * 256 + k] = __float2bfloat16(r);
}

// embed: h0 = relu(x @ We + be), written directly as split bf16
__global__ __launch_bounds__(256) void embed_kernel(
    const float* __restrict__ x, const float* __restrict__ W,
    const float* __restrict__ b,
    __nv_bfloat16* __restrict__ hhi, __nv_bfloat16* __restrict__ hlo, int n)
{
    __shared__ float xs[8][F_IN];
    int j = threadIdx.x;
    int node0 = blockIdx.x * 8;
    int t = threadIdx.x;
    if (t < 8 * F_IN) {
        int nn = t / F_IN, kk = t % F_IN;
        int gi = node0 + nn;
        xs[nn][kk] = (gi < n) ? x[gi * F_IN + kk] : 0.0f;
    }
    __syncthreads();
    float wcol[F_IN];
#pragma unroll
    for (int k = 0; k < F_IN; k++) wcol[k] = W[k * D + j];
    float bj = b[j];
#pragma unroll
    for (int nn = 0; nn < 8; nn++) {
        int gi = node0 + nn;
        if (gi >= n) return;
        float s = bj;
#pragma unroll
        for (int k = 0; k < F_IN; k++) s = fmaf(xs[nn][k], wcol[k], s);
        s = fmaxf(s, 0.0f);
        __nv_bfloat16 h = __float2bfloat16(s);
        hhi[gi * D + j] = h;
        hlo[gi * D + j] = __float2bfloat16(s - __bfloat162float(h));
    }
}

// relu + split: a_{hi,lo} = split(relu(ag))
__global__ __launch_bounds__(256) void relu_split(
    const float* __restrict__ ag,
    __nv_bfloat16* __restrict__ ahi, __nv_bfloat16* __restrict__ alo, int n)
{
    int v = blockIdx.x * 256 + threadIdx.x;     // over n*64 float4s
    if (v >= n * 64) return;
    float4 a = ((const float4*)ag)[v];
    a.x = fmaxf(a.x, 0.f); a.y = fmaxf(a.y, 0.f);
    a.z = fmaxf(a.z, 0.f); a.w = fmaxf(a.w, 0.f);
    uint2 h, l;
    split2(a.x, a.y, h.x, l.x);
    split2(a.z, a.w, h.y, l.y);
    ((uint2*)ahi)[v] = h;
    ((uint2*)alo)[v] = l;
}

// ======================= bf16-split tensor-core GEMM (pre-split inputs) ======
// Chw[M,256] = A[M,256] @ Wt^T;  Cag = Chw*dinv[row]^2 + bias
// A given as bf16 hi/lo row-major; Wt given as bf16 hi/lo [n][k].
// BM=128, BN=64, BK=32; 8 warps x (32x32) out; 3-term bf16 emulation.
// Double-buffered cp.async pipeline, 80B smem row pitch (conflict-free ldmatrix).
#define BM 128
#define BN 64
#define BK 32
#define ROWB 80u                 // bytes per smem row (32 bf16 + 8 pad)
#define A_HI 0u
#define A_LO 10240u
#define B_HI 20480u
#define B_LO 25600u
#define STAGE_B 30720u
#define GEMM_SMEM (2 * 30720)

__global__ __launch_bounds__(256, 2) void gemm_mma(
    const __nv_bfloat16* __restrict__ Ahi, const __nv_bfloat16* __restrict__ Alo,
    const __nv_bfloat16* __restrict__ Bhi, const __nv_bfloat16* __restrict__ Blo,
    const float* __restrict__ bias, const float* __restrict__ dinv,
    float* __restrict__ Chw, float* __restrict__ Cag, int M)
{
    extern __shared__ char smem[];
    const uint32_t sb0 = smem_u32(smem);
    const int t   = threadIdx.x;
    const int wid = t >> 5, lid = t & 31;
    const int m0  = blockIdx.y * BM;
    const int n0  = blockIdx.x * BN;
    const int wm  = wid & 3;          // 4 warp-rows of 32
    const int wn  = wid >> 2;         // 2 warp-cols of 32

    float acc[2][4][4];
#pragma unroll
    for (int i = 0; i < 2; i++)
#pragma unroll
        for (int j = 0; j < 4; j++)
#pragma unroll
            for (int k = 0; k < 4; k++) acc[i][j][k] = 0.0f;

    const int a_r16 = lid & 15, a_kh = lid >> 4;
    const int b_n8  = lid & 7,  b_kh = (lid >> 3) & 1;

    // ---- tile loader: 6 cp.async x 16B per thread ----
    auto issue = [&](int st, int stage) {
        const int kc = st * BK;
        const uint32_t sb = sb0 + stage * STAGE_B;
#pragma unroll
        for (int tt = t; tt < 512; tt += 256) {       // A: 128 rows x 4 chunks
            int row = tt >> 2, ch = tt & 3;
            int gr = m0 + row;
            uint32_t sz = (gr < M) ? 16u : 0u;
            int gc = (gr < M) ? gr : (M - 1);
            size_t e = (size_t)gc * 256 + kc + ch * 8;
            uint32_t dst = sb + row * ROWB + ch * 16u;
            cp16(dst + A_HI, Ahi + e, sz);
            cp16(dst + A_LO, Alo + e, sz);
        }
        {                                             // B: 64 rows x 4 chunks
            int row = t >> 2, ch = t & 3;
            size_t e = (size_t)(n0 + row) * 256 + kc + ch * 8;
            uint32_t dst = sb + row * ROWB + ch * 16u;
            cp16(dst + B_HI, Bhi + e, 16u);
            cp16(dst + B_LO, Blo + e, 16u);
        }
    };

    issue(0, 0); CP_COMMIT();

#pragma unroll 1
    for (int st = 0; st < 256 / BK; st++) {
        const int cur = st & 1;
        if (st < 7) { issue(st + 1, cur ^ 1); CP_COMMIT(); CP_WAIT(1); }
        else        { CP_WAIT(0); }
        __syncthreads();

        const uint32_t sA = sb0 + cur * STAGE_B;
        const uint32_t sAhi = sA + A_HI, sAlo = sA + A_LO;
        const uint32_t sBhi = sA + B_HI, sBlo = sA + B_LO;

#pragma unroll
        for (int ks = 0; ks < 2; ks++) {
            const int kb = ks * 16;
            uint32_t ah[2][4], al[2][4];
#pragma unroll
            for (int mt = 0; mt < 2; mt++) {
                uint32_t off = (uint32_t)(wm * 32 + mt * 16 + a_r16) * ROWB
                             + (uint32_t)(kb + a_kh * 8) * 2;
                ldm_x4(ah[mt], sAhi + off);
                ldm_x4(al[mt], sAlo + off);
            }
            uint32_t bh[4][2], bl[4][2];
#pragma unroll
            for (int nt = 0; nt < 4; nt++) {
                uint32_t off = (uint32_t)(wn * 32 + nt * 8 + b_n8) * ROWB
                             + (uint32_t)(kb + b_kh * 8) * 2;
                ldm_x2(bh[nt], sBhi + off);
                ldm_x2(bl[nt], sBlo + off);
            }
#pragma unroll
            for (int mt = 0; mt < 2; mt++)
#pragma unroll
                for (int nt = 0; nt < 4; nt++) {
                    mma_bf16(acc[mt][nt], ah[mt], bh[nt]);
                    mma_bf16(acc[mt][nt], ah[mt], bl[nt]);
                    mma_bf16(acc[mt][nt], al[mt], bh[nt]);
                }
        }
        __syncthreads();
    }

    // ---- epilogue: write hw and ag = hw*dinv^2 + bias ----
    const int rbase = m0 + wm * 32 + (lid >> 2);
    const int cbase = n0 + wn * 32 + (lid & 3) * 2;
#pragma unroll
    for (int nt = 0; nt < 4; nt++) {
        const int col = cbase + nt * 8;
        float2 bb = make_float2(bias[col], bias[col + 1]);
#pragma unroll
        for (int mt = 0; mt < 2; mt++) {
#pragma unroll
            for (int h = 0; h < 2; h++) {       // row, row+8
                int row = rbase + mt * 16 + h * 8;
                if (row < M) {
                    float vx = acc[mt][nt][2 * h + 0];
                    float vy = acc[mt][nt][2 * h + 1];
                    size_t off = (size_t)row * 256 + col;
                    *(float2*)(Chw + off) = make_float2(vx, vy);
                    float s = dinv[row]; s = s * s;
                    *(float2*)(Cag + off) =
                        make_float2(fmaf(vx, s, bb.x), fmaf(vy, s, bb.y));
                }
            }
        }
    }
}

// ======================= edge scatter =======================
__global__ void scatter_kernel(const float* __restrict__ hw,
                               const int* __restrict__ src,
                               const int* __restrict__ dst,
                               const float* __restrict__ dinv,
                               float* __restrict__ out, int e)
{
    long long t = (long long)blockIdx.x * blockDim.x + threadIdx.x;
    int ei   = (int)(t >> 6);
    int lane = (int)(t & 63);
    if (ei >= e) return;
    int s = src[ei];
    int d = dst[ei];
    float norm = dinv[s] * dinv[d];
    float4 v = ((const float4*)hw)[s * 64 + lane];
    float* o = out + (size_t)d * 256 + lane * 4;
    asm volatile("red.global.add.v4.f32 [%0], {%1,%2,%3,%4};"
                 :: "l"(o), "f"(v.x * norm), "f"(v.y * norm),
                    "f"(v.z * norm), "f"(v.w * norm)
                 : "memory");
}

// ======================= launch =======================
extern "C" void kernel_launch(void* const* d_in, const int* in_sizes, int n_in,
                              void* d_out, int out_size)
{
    const float* x  = (const float*)d_in[0];
    const int*   ei = (const int*)  d_in[1];
    const float* We = (const float*)d_in[2];
    const float* be = (const float*)d_in[3];
    const float* W1 = (const float*)d_in[4];
    const float* b1 = (const float*)d_in[5];
    const float* W2 = (const float*)d_in[6];
    const float* b2 = (const float*)d_in[7];
    float* out = (float*)d_out;

    const int N = in_sizes[0] / F_IN;       // 50000
    const int E = in_sizes[1] / 2;          // 300000
    const int* src = ei;
    const int* dst = ei + E;

    float* dinv = nullptr; cudaGetSymbolAddress((void**)&dinv, g_dinv);
    float* hw   = nullptr; cudaGetSymbolAddress((void**)&hw,   g_hw);
    float* ag   = nullptr; cudaGetSymbolAddress((void**)&ag,   g_ag);
    __nv_bfloat16 *ahi, *alo, *w1hi, *w1lo, *w2hi, *w2lo;
    cudaGetSymbolAddress((void**)&ahi,  g_ahi);
    cudaGetSymbolAddress((void**)&alo,  g_alo);
    cudaGetSymbolAddress((void**)&w1hi, g_w1hi);
    cudaGetSymbolAddress((void**)&w1lo, g_w1lo);
    cudaGetSymbolAddress((void**)&w2hi, g_w2hi);
    cudaGetSymbolAddress((void**)&w2lo, g_w2lo);

    cudaFuncSetAttribute(gemm_mma, cudaFuncAttributeMaxDynamicSharedMemorySize, GEMM_SMEM);

    // degree / normalization
    deg_init <<<(N + 255) / 256, 256>>>(dinv, N);
    deg_count<<<(E + 255) / 256, 256>>>(dst, dinv, E);
    deg_rsqrt<<<(N + 255) / 256, 256>>>(dinv, N);

    // one-time weight split (transposed)
    wt_split<<<D * D / 256, 256>>>(W1, w1hi, w1lo);
    wt_split<<<D * D / 256, 256>>>(W2, w2hi, w2lo);

    // embed + relu -> split bf16
    embed_kernel<<<(N + 7) / 8, 256>>>(x, We, be, ahi, alo, N);

    dim3 gg(D / BN, (N + BM - 1) / BM);     // (4, 391)

    // layer 1
    gemm_mma<<<gg, 256, GEMM_SMEM>>>(ahi, alo, w1hi, w1lo, b1, dinv, hw, ag, N);
    scatter_kernel<<<((long long)E * 64 + 255) / 256, 256>>>(hw, src, dst, dinv, ag, E);
    relu_split<<<(N * 64 + 255) / 256, 256>>>(ag, ahi, alo, N);

    // layer 2
    gemm_mma<<<gg, 256, GEMM_SMEM>>>(ahi, alo, w2hi, w2lo, b2, dinv, hw, out, N);
    scatter_kernel<<<((long long)E * 64 + 255) / 256, 256>>>(hw, src, dst, dinv, out, E);
}

// round 14
// speedup vs baseline: 4.6906x; 1.3540x over previous
#include <cuda_runtime.h>
#include <cuda_bf16.h>
#include <cstdint>

#define N_NODES 50000
#define N_EDGES 300000
#define F_IN 11
#define D 256

// Scratch (bss globals, allowed per harness rules)
__device__ float g_dinv[N_NODES];
__device__ float g_hw [N_NODES * D];
// CSR by destination
__device__ int g_cnt   [N_NODES];
__device__ int g_cur   [N_NODES];
__device__ int g_rowptr[N_NODES];
__device__ int g_bsum  [256];
__device__ int g_csr   [N_EDGES];
// split bf16 activation buffers (h0 for layer1, relu(agg1) for layer2)
__device__ __nv_bfloat16 g_ahi[N_NODES * D];
__device__ __nv_bfloat16 g_alo[N_NODES * D];
// split, transposed weights: Wt[n][k] = W[k][n]
__device__ __nv_bfloat16 g_w1hi[D * D], g_w1lo[D * D];
__device__ __nv_bfloat16 g_w2hi[D * D], g_w2lo[D * D];

// ======================= helpers =======================
__device__ __forceinline__ uint32_t smem_u32(const void* p) {
    uint32_t a;
    asm("{ .reg .u64 t; cvta.to.shared.u64 t, %1; cvt.u32.u64 %0, t; }" : "=r"(a) : "l"(p));
    return a;
}
// split (v0,v1) into packed bf16x2 hi + bf16x2 residual lo (lane0 = low half)
__device__ __forceinline__ void split2(float v0, float v1, uint32_t& hi, uint32_t& lo) {
    uint32_t h;
    asm("cvt.rn.bf16x2.f32 %0, %1, %2;" : "=r"(h) : "f"(v1), "f"(v0));
    float r0 = v0 - __uint_as_float(h << 16);
    float r1 = v1 - __uint_as_float(h & 0xFFFF0000u);
    uint32_t l;
    asm("cvt.rn.bf16x2.f32 %0, %1, %2;" : "=r"(l) : "f"(r1), "f"(r0));
    hi = h; lo = l;
}
__device__ __forceinline__ void ldm_x4(uint32_t* r, uint32_t addr) {
    asm volatile("ldmatrix.sync.aligned.m8n8.x4.shared.b16 {%0,%1,%2,%3}, [%4];"
                 : "=r"(r[0]), "=r"(r[1]), "=r"(r[2]), "=r"(r[3]) : "r"(addr));
}
__device__ __forceinline__ void ldm_x2(uint32_t* r, uint32_t addr) {
    asm volatile("ldmatrix.sync.aligned.m8n8.x2.shared.b16 {%0,%1}, [%2];"
                 : "=r"(r[0]), "=r"(r[1]) : "r"(addr));
}
__device__ __forceinline__ void mma_bf16(float* c, const uint32_t* a, const uint32_t* b) {
    asm volatile("mma.sync.aligned.m16n8k16.row.col.f32.bf16.bf16.f32 "
                 "{%0,%1,%2,%3}, {%4,%5,%6,%7}, {%8,%9}, {%0,%1,%2,%3};"
                 : "+f"(c[0]), "+f"(c[1]), "+f"(c[2]), "+f"(c[3])
                 : "r"(a[0]), "r"(a[1]), "r"(a[2]), "r"(a[3]), "r"(b[0]), "r"(b[1]));
}
__device__ __forceinline__ void cp16(uint32_t dst, const __nv_bfloat16* src, uint32_t sz) {
    uint64_t g;
    asm("cvta.to.global.u64 %0, %1;" : "=l"(g) : "l"(src));
    asm volatile("cp.async.cg.shared.global [%0], [%1], 16, %2;"
                 :: "r"(dst), "l"(g), "r"(sz) : "memory");
}
#define CP_COMMIT() asm volatile("cp.async.commit_group;" ::: "memory")
#define CP_WAIT(n)  asm volatile("cp.async.wait_group %0;" :: "n"(n) : "memory")

// ======================= CSR build =======================
__global__ void cnt_zero(int* cnt, int n) {
    int i = blockIdx.x * blockDim.x + threadIdx.x;
    if (i < n) cnt[i] = 0;
}
__global__ void cnt_count(const int* __restrict__ dst, int* cnt, int e) {
    int i = blockIdx.x * blockDim.x + threadIdx.x;
    if (i < e) atomicAdd(&cnt[dst[i]], 1);
}
__global__ void deg_rsqrt_k(const int* __restrict__ cnt, float* dinv, int n) {
    int i = blockIdx.x * blockDim.x + threadIdx.x;
    if (i < n) dinv[i] = rsqrtf((float)(cnt[i] + 1));   // +1 self-loop
}
// exclusive scan, 256 per block
__global__ void scan_local(const int* __restrict__ cnt, int* exc, int* bsum, int n) {
    __shared__ int s[256];
    int i = blockIdx.x * 256 + threadIdx.x;
    int v = (i < n) ? cnt[i] : 0;
    s[threadIdx.x] = v;
    __syncthreads();
#pragma unroll
    for (int d2 = 1; d2 < 256; d2 <<= 1) {
        int t = (threadIdx.x >= d2) ? s[threadIdx.x - d2] : 0;
        __syncthreads();
        s[threadIdx.x] += t;
        __syncthreads();
    }
    if (i < n) exc[i] = s[threadIdx.x] - v;
    if (threadIdx.x == 255) bsum[blockIdx.x] = s[255];
}
__global__ void scan_tops(int* bsum, int nb) {   // single block, nb <= 256
    __shared__ int s[256];
    int v = (threadIdx.x < nb) ? bsum[threadIdx.x] : 0;
    s[threadIdx.x] = v;
    __syncthreads();
#pragma unroll
    for (int d2 = 1; d2 < 256; d2 <<= 1) {
        int t = (threadIdx.x >= d2) ? s[threadIdx.x - d2] : 0;
        __syncthreads();
        s[threadIdx.x] += t;
        __syncthreads();
    }
    if (threadIdx.x < nb) bsum[threadIdx.x] = s[threadIdx.x] - v;   // exclusive
}
__global__ void scan_add(const int* __restrict__ exc, const int* __restrict__ bsum,
                         int* rowptr, int* cur, int n) {
    int i = blockIdx.x * 256 + threadIdx.x;
    if (i < n) {
        int off = exc[i] + bsum[blockIdx.x];
        rowptr[i] = off;
        cur[i] = off;
    }
}
__global__ void csr_fill(const int* __restrict__ src, const int* __restrict__ dst,
                         int* cur, int* csr, int e) {
    int i = blockIdx.x * blockDim.x + threadIdx.x;
    if (i < e) {
        int slot = atomicAdd(&cur[dst[i]], 1);
        csr[slot] = src[i];
    }
}

// ======================= weight split (transposed, one-time) =======================
__global__ __launch_bounds__(256) void wt_split(
    const float* __restrict__ W,
    __nv_bfloat16* __restrict__ Whi, __nv_bfloat16* __restrict__ Wlo)
{
    int idx = blockIdx.x * 256 + threadIdx.x;   // 65536 total
    int k = idx >> 8, n = idx & 255;
    float v = W[k * 256 + n];
    __nv_bfloat16 h = __float2bfloat16(v);
    float r = v - __bfloat162float(h);
    Whi[n * 256 + k] = h;
    Wlo[n * 256 + k] = __float2bfloat16(r);
}

// ======================= embed: split bf16 of relu(x @ We + be) =======================
__global__ __launch_bounds__(256) void embed_kernel(
    const float* __restrict__ x, const float* __restrict__ W,
    const float* __restrict__ b,
    __nv_bfloat16* __restrict__ hhi, __nv_bfloat16* __restrict__ hlo, int n)
{
    __shared__ float xs[8][F_IN];
    int j = threadIdx.x;
    int node0 = blockIdx.x * 8;
    int t = threadIdx.x;
    if (t < 8 * F_IN) {
        int nn = t / F_IN, kk = t % F_IN;
        int gi = node0 + nn;
        xs[nn][kk] = (gi < n) ? x[gi * F_IN + kk] : 0.0f;
    }
    __syncthreads();
    float wcol[F_IN];
#pragma unroll
    for (int k = 0; k < F_IN; k++) wcol[k] = W[k * D + j];
    float bj = b[j];
#pragma unroll
    for (int nn = 0; nn < 8; nn++) {
        int gi = node0 + nn;
        if (gi >= n) return;
        float s = bj;
#pragma unroll
        for (int k = 0; k < F_IN; k++) s = fmaf(xs[nn][k], wcol[k], s);
        s = fmaxf(s, 0.0f);
        __nv_bfloat16 h = __float2bfloat16(s);
        hhi[gi * D + j] = h;
        hlo[gi * D + j] = __float2bfloat16(s - __bfloat162float(h));
    }
}

// ======================= bf16-split tensor-core GEMM =======================
// Chw[M,256] = A[M,256] @ Wt^T  (writes hw only; aggregation handled by gather)
#define BM 128
#define BN 64
#define BK 32
#define ROWB 80u
#define A_HI 0u
#define A_LO 10240u
#define B_HI 20480u
#define B_LO 25600u
#define STAGE_B 30720u
#define GEMM_SMEM (2 * 30720)

__global__ __launch_bounds__(256, 2) void gemm_mma(
    const __nv_bfloat16* __restrict__ Ahi, const __nv_bfloat16* __restrict__ Alo,
    const __nv_bfloat16* __restrict__ Bhi, const __nv_bfloat16* __restrict__ Blo,
    float* __restrict__ Chw, int M)
{
    extern __shared__ char smem[];
    const uint32_t sb0 = smem_u32(smem);
    const int t   = threadIdx.x;
    const int wid = t >> 5, lid = t & 31;
    const int m0  = blockIdx.y * BM;
    const int n0  = blockIdx.x * BN;
    const int wm  = wid & 3;
    const int wn  = wid >> 2;

    float acc[2][4][4];
#pragma unroll
    for (int i = 0; i < 2; i++)
#pragma unroll
        for (int j = 0; j < 4; j++)
#pragma unroll
            for (int k = 0; k < 4; k++) acc[i][j][k] = 0.0f;

    const int a_r16 = lid & 15, a_kh = lid >> 4;
    const int b_n8  = lid & 7,  b_kh = (lid >> 3) & 1;

    auto issue = [&](int st, int stage) {
        const int kc = st * BK;
        const uint32_t sb = sb0 + stage * STAGE_B;
#pragma unroll
        for (int tt = t; tt < 512; tt += 256) {
            int row = tt >> 2, ch = tt & 3;
            int gr = m0 + row;
            uint32_t sz = (gr < M) ? 16u : 0u;
            int gc = (gr < M) ? gr : (M - 1);
            size_t e = (size_t)gc * 256 + kc + ch * 8;
            uint32_t dst = sb + row * ROWB + ch * 16u;
            cp16(dst + A_HI, Ahi + e, sz);
            cp16(dst + A_LO, Alo + e, sz);
        }
        {
            int row = t >> 2, ch = t & 3;
            size_t e = (size_t)(n0 + row) * 256 + kc + ch * 8;
            uint32_t dst = sb + row * ROWB + ch * 16u;
            cp16(dst + B_HI, Bhi + e, 16u);
            cp16(dst + B_LO, Blo + e, 16u);
        }
    };

    issue(0, 0); CP_COMMIT();

#pragma unroll 1
    for (int st = 0; st < 256 / BK; st++) {
        const int cur = st & 1;
        if (st < 7) { issue(st + 1, cur ^ 1); CP_COMMIT(); CP_WAIT(1); }
        else        { CP_WAIT(0); }
        __syncthreads();

        const uint32_t sA = sb0 + cur * STAGE_B;
        const uint32_t sAhi = sA + A_HI, sAlo = sA + A_LO;
        const uint32_t sBhi = sA + B_HI, sBlo = sA + B_LO;

#pragma unroll
        for (int ks = 0; ks < 2; ks++) {
            const int kb = ks * 16;
            uint32_t ah[2][4], al[2][4];
#pragma unroll
            for (int mt = 0; mt < 2; mt++) {
                uint32_t off = (uint32_t)(wm * 32 + mt * 16 + a_r16) * ROWB
                             + (uint32_t)(kb + a_kh * 8) * 2;
                ldm_x4(ah[mt], sAhi + off);
                ldm_x4(al[mt], sAlo + off);
            }
            uint32_t bh[4][2], bl[4][2];
#pragma unroll
            for (int nt = 0; nt < 4; nt++) {
                uint32_t off = (uint32_t)(wn * 32 + nt * 8 + b_n8) * ROWB
                             + (uint32_t)(kb + b_kh * 8) * 2;
                ldm_x2(bh[nt], sBhi + off);
                ldm_x2(bl[nt], sBlo + off);
            }
#pragma unroll
            for (int mt = 0; mt < 2; mt++)
#pragma unroll
                for (int nt = 0; nt < 4; nt++) {
                    mma_bf16(acc[mt][nt], ah[mt], bh[nt]);
                    mma_bf16(acc[mt][nt], ah[mt], bl[nt]);
                    mma_bf16(acc[mt][nt], al[mt], bh[nt]);
                }
        }
        __syncthreads();
    }

    const int rbase = m0 + wm * 32 + (lid >> 2);
    const int cbase = n0 + wn * 32 + (lid & 3) * 2;
#pragma unroll
    for (int nt = 0; nt < 4; nt++) {
        const int col = cbase + nt * 8;
#pragma unroll
        for (int mt = 0; mt < 2; mt++) {
#pragma unroll
            for (int h = 0; h < 2; h++) {
                int row = rbase + mt * 16 + h * 8;
                if (row < M)
                    *(float2*)(Chw + (size_t)row * 256 + col) =
                        make_float2(acc[mt][nt][2 * h + 0], acc[mt][nt][2 * h + 1]);
            }
        }
    }
}

// ======================= CSR gather (replaces atomic scatter) ==================
// For node d: acc = hw[d]*dinv[d]^2 + bias + sum_{s in in(d)} hw[s]*dinv[s]*dinv[d]
// L1: writes relu+split bf16 into ahi/alo.  L2: writes fp32 out.
template <bool L1>
__global__ __launch_bounds__(64) void gather_k(
    const float* __restrict__ hw,
    const int* __restrict__ rowptr, const int* __restrict__ cnt,
    const int* __restrict__ csr, const float* __restrict__ dinv,
    const float* __restrict__ bias,
    float* __restrict__ outf,
    __nv_bfloat16* __restrict__ ahi, __nv_bfloat16* __restrict__ alo)
{
    __shared__ int   ss[64];
    __shared__ float ws[64];
    const int d = blockIdx.x;
    const int lane = threadIdx.x;
    const float dd = dinv[d];
    const float s2 = dd * dd;

    float4 h = ((const float4*)hw)[(size_t)d * 64 + lane];
    float4 bb = ((const float4*)bias)[lane];
    float4 acc;
    acc.x = fmaf(h.x, s2, bb.x);
    acc.y = fmaf(h.y, s2, bb.y);
    acc.z = fmaf(h.z, s2, bb.z);
    acc.w = fmaf(h.w, s2, bb.w);

    const int beg = rowptr[d];
    const int c   = cnt[d];
    for (int base = 0; base < c; base += 64) {
        int m = min(64, c - base);
        __syncthreads();
        if (lane < m) {
            int s = csr[beg + base + lane];
            ss[lane] = s;
            ws[lane] = dinv[s] * dd;
        }
        __syncthreads();
#pragma unroll 4
        for (int j = 0; j < m; j++) {
            float w = ws[j];
            float4 v = ((const float4*)hw)[(size_t)ss[j] * 64 + lane];
            acc.x = fmaf(v.x, w, acc.x);
            acc.y = fmaf(v.y, w, acc.y);
            acc.z = fmaf(v.z, w, acc.z);
            acc.w = fmaf(v.w, w, acc.w);
        }
    }

    if (L1) {
        acc.x = fmaxf(acc.x, 0.f); acc.y = fmaxf(acc.y, 0.f);
        acc.z = fmaxf(acc.z, 0.f); acc.w = fmaxf(acc.w, 0.f);
        uint2 hv, lv;
        split2(acc.x, acc.y, hv.x, lv.x);
        split2(acc.z, acc.w, hv.y, lv.y);
        ((uint2*)ahi)[(size_t)d * 64 + lane] = hv;
        ((uint2*)alo)[(size_t)d * 64 + lane] = lv;
    } else {
        ((float4*)outf)[(size_t)d * 64 + lane] = acc;
    }
}

// ======================= launch =======================
extern "C" void kernel_launch(void* const* d_in, const int* in_sizes, int n_in,
                              void* d_out, int out_size)
{
    const float* x  = (const float*)d_in[0];
    const int*   ei = (const int*)  d_in[1];
    const float* We = (const float*)d_in[2];
    const float* be = (const float*)d_in[3];
    const float* W1 = (const float*)d_in[4];
    const float* b1 = (const float*)d_in[5];
    const float* W2 = (const float*)d_in[6];
    const float* b2 = (const float*)d_in[7];
    float* out = (float*)d_out;

    const int N = in_sizes[0] / F_IN;       // 50000
    const int E = in_sizes[1] / 2;          // 300000
    const int* src = ei;
    const int* dst = ei + E;

    float* dinv; cudaGetSymbolAddress((void**)&dinv, g_dinv);
    float* hw;   cudaGetSymbolAddress((void**)&hw,   g_hw);
    int *cnt, *cur, *rowptr, *bsum, *csr;
    cudaGetSymbolAddress((void**)&cnt,    g_cnt);
    cudaGetSymbolAddress((void**)&cur,    g_cur);
    cudaGetSymbolAddress((void**)&rowptr, g_rowptr);
    cudaGetSymbolAddress((void**)&bsum,   g_bsum);
    cudaGetSymbolAddress((void**)&csr,    g_csr);
    __nv_bfloat16 *ahi, *alo, *w1hi, *w1lo, *w2hi, *w2lo;
    cudaGetSymbolAddress((void**)&ahi,  g_ahi);
    cudaGetSymbolAddress((void**)&alo,  g_alo);
    cudaGetSymbolAddress((void**)&w1hi, g_w1hi);
    cudaGetSymbolAddress((void**)&w1lo, g_w1lo);
    cudaGetSymbolAddress((void**)&w2hi, g_w2hi);
    cudaGetSymbolAddress((void**)&w2lo, g_w2lo);

    cudaFuncSetAttribute(gemm_mma, cudaFuncAttributeMaxDynamicSharedMemorySize, GEMM_SMEM);

    const int nb = (N + 255) / 256;         // 196 <= 256

    // ---- CSR build + normalization ----
    cnt_zero <<<nb, 256>>>(cnt, N);
    cnt_count<<<(E + 255) / 256, 256>>>(dst, cnt, E);
    deg_rsqrt_k<<<nb, 256>>>(cnt, dinv, N);
    scan_local<<<nb, 256>>>(cnt, rowptr, bsum, N);   // rowptr as temp exc
    scan_tops <<<1, 256>>>(bsum, nb);
    scan_add  <<<nb, 256>>>(rowptr, bsum, rowptr, cur, N);
    csr_fill  <<<(E + 255) / 256, 256>>>(src, dst, cur, csr, E);

    // ---- one-time weight split (transposed) ----
    wt_split<<<D * D / 256, 256>>>(W1, w1hi, w1lo);
    wt_split<<<D * D / 256, 256>>>(W2, w2hi, w2lo);

    // ---- embed + relu -> split bf16 ----
    embed_kernel<<<(N + 7) / 8, 256>>>(x, We, be, ahi, alo, N);

    dim3 gg(D / BN, (N + BM - 1) / BM);     // (4, 391)

    // layer 1: hw = h0 @ W1 ; gather (self+bias+edges) -> relu+split -> ahi/alo
    gemm_mma<<<gg, 256, GEMM_SMEM>>>(ahi, alo, w1hi, w1lo, hw, N);
    gather_k<true><<<N, 64>>>(hw, rowptr, cnt, csr, dinv, b1, nullptr, ahi, alo);

    // layer 2: hw = a @ W2 ; gather -> out
    gemm_mma<<<gg, 256, GEMM_SMEM>>>(ahi, alo, w2hi, w2lo, hw, N);
    gather_k<false><<<N, 64>>>(hw, rowptr, cnt, csr, dinv, b2, out, nullptr, nullptr);
}

// round 15
// speedup vs baseline: 5.7144x; 1.2183x over previous
#include <cuda_runtime.h>
#include <cuda_fp16.h>
#include <cstdint>

#define N_NODES 50000
#define N_EDGES 300000
#define F_IN 11
#define D 256

// Scratch (bss globals, allowed per harness rules)
__device__ float g_dinv[N_NODES];
__device__ float g_hw [N_NODES * D];
// CSR by destination
__device__ int g_cnt   [N_NODES];
__device__ int g_cur   [N_NODES];
__device__ int g_rowptr[N_NODES];
__device__ int g_bsum  [256];
__device__ int g_csr   [N_EDGES];
// fp16 activation buffer (h0 for layer1, relu(agg1) for layer2)
__device__ __half g_a[N_NODES * D];
// split, transposed weights: Wt[n][k] = W[k][n], fp16 hi + residual lo
__device__ __half g_w1hi[D * D], g_w1lo[D * D];
__device__ __half g_w2hi[D * D], g_w2lo[D * D];

// ======================= helpers =======================
__device__ __forceinline__ uint32_t smem_u32(const void* p) {
    uint32_t a;
    asm("{ .reg .u64 t; cvta.to.shared.u64 t, %1; cvt.u32.u64 %0, t; }" : "=r"(a) : "l"(p));
    return a;
}
__device__ __forceinline__ void ldm_x4(uint32_t* r, uint32_t addr) {
    asm volatile("ldmatrix.sync.aligned.m8n8.x4.shared.b16 {%0,%1,%2,%3}, [%4];"
                 : "=r"(r[0]), "=r"(r[1]), "=r"(r[2]), "=r"(r[3]) : "r"(addr));
}
__device__ __forceinline__ void ldm_x2(uint32_t* r, uint32_t addr) {
    asm volatile("ldmatrix.sync.aligned.m8n8.x2.shared.b16 {%0,%1}, [%2];"
                 : "=r"(r[0]), "=r"(r[1]) : "r"(addr));
}
__device__ __forceinline__ void mma_fp16(float* c, const uint32_t* a, const uint32_t* b) {
    asm volatile("mma.sync.aligned.m16n8k16.row.col.f32.f16.f16.f32 "
                 "{%0,%1,%2,%3}, {%4,%5,%6,%7}, {%8,%9}, {%0,%1,%2,%3};"
                 : "+f"(c[0]), "+f"(c[1]), "+f"(c[2]), "+f"(c[3])
                 : "r"(a[0]), "r"(a[1]), "r"(a[2]), "r"(a[3]), "r"(b[0]), "r"(b[1]));
}
__device__ __forceinline__ void cp16(uint32_t dst, const __half* src, uint32_t sz) {
    uint64_t g;
    asm("cvta.to.global.u64 %0, %1;" : "=l"(g) : "l"(src));
    asm volatile("cp.async.cg.shared.global [%0], [%1], 16, %2;"
                 :: "r"(dst), "l"(g), "r"(sz) : "memory");
}
#define CP_COMMIT() asm volatile("cp.async.commit_group;" ::: "memory")
#define CP_WAIT(n)  asm volatile("cp.async.wait_group %0;" :: "n"(n) : "memory")

// ======================= CSR build =======================
__global__ void cnt_zero(int* cnt, int n) {
    int i = blockIdx.x * blockDim.x + threadIdx.x;
    if (i < n) cnt[i] = 0;
}
__global__ void cnt_count(const int* __restrict__ dst, int* cnt, int e) {
    int i = blockIdx.x * blockDim.x + threadIdx.x;
    if (i < e) atomicAdd(&cnt[dst[i]], 1);
}
__global__ void deg_rsqrt_k(const int* __restrict__ cnt, float* dinv, int n) {
    int i = blockIdx.x * blockDim.x + threadIdx.x;
    if (i < n) dinv[i] = rsqrtf((float)(cnt[i] + 1));   // +1 self-loop
}
__global__ void scan_local(const int* __restrict__ cnt, int* exc, int* bsum, int n) {
    __shared__ int s[256];
    int i = blockIdx.x * 256 + threadIdx.x;
    int v = (i < n) ? cnt[i] : 0;
    s[threadIdx.x] = v;
    __syncthreads();
#pragma unroll
    for (int d2 = 1; d2 < 256; d2 <<= 1) {
        int t = (threadIdx.x >= d2) ? s[threadIdx.x - d2] : 0;
        __syncthreads();
        s[threadIdx.x] += t;
        __syncthreads();
    }
    if (i < n) exc[i] = s[threadIdx.x] - v;
    if (threadIdx.x == 255) bsum[blockIdx.x] = s[255];
}
__global__ void scan_tops(int* bsum, int nb) {   // single block, nb <= 256
    __shared__ int s[256];
    int v = (threadIdx.x < nb) ? bsum[threadIdx.x] : 0;
    s[threadIdx.x] = v;
    __syncthreads();
#pragma unroll
    for (int d2 = 1; d2 < 256; d2 <<= 1) {
        int t = (threadIdx.x >= d2) ? s[threadIdx.x - d2] : 0;
        __syncthreads();
        s[threadIdx.x] += t;
        __syncthreads();
    }
    if (threadIdx.x < nb) bsum[threadIdx.x] = s[threadIdx.x] - v;   // exclusive
}
__global__ void scan_add(const int* __restrict__ exc, const int* __restrict__ bsum,
                         int* rowptr, int* cur, int n) {
    int i = blockIdx.x * 256 + threadIdx.x;
    if (i < n) {
        int off = exc[i] + bsum[blockIdx.x];
        rowptr[i] = off;
        cur[i] = off;
    }
}
__global__ void csr_fill(const int* __restrict__ src, const int* __restrict__ dst,
                         int* cur, int* csr, int e) {
    int i = blockIdx.x * blockDim.x + threadIdx.x;
    if (i < e) {
        int slot = atomicAdd(&cur[dst[i]], 1);
        csr[slot] = src[i];
    }
}

// ======================= weight split (transposed, one-time) =======================
__global__ __launch_bounds__(256) void wt_split(
    const float* __restrict__ W,
    __half* __restrict__ Whi, __half* __restrict__ Wlo)
{
    int idx = blockIdx.x * 256 + threadIdx.x;   // 65536 total
    int k = idx >> 8, n = idx & 255;
    float v = W[k * 256 + n];
    __half h = __float2half_rn(v);
    float r = v - __half2float(h);
    Whi[n * 256 + k] = h;
    Wlo[n * 256 + k] = __float2half_rn(r);
}

// ======================= embed: fp16 of relu(x @ We + be) =======================
__global__ __launch_bounds__(256) void embed_kernel(
    const float* __restrict__ x, const float* __restrict__ W,
    const float* __restrict__ b, __half* __restrict__ ha, int n)
{
    __shared__ float xs[8][F_IN];
    int j = threadIdx.x;
    int node0 = blockIdx.x * 8;
    int t = threadIdx.x;
    if (t < 8 * F_IN) {
        int nn = t / F_IN, kk = t % F_IN;
        int gi = node0 + nn;
        xs[nn][kk] = (gi < n) ? x[gi * F_IN + kk] : 0.0f;
    }
    __syncthreads();
    float wcol[F_IN];
#pragma unroll
    for (int k = 0; k < F_IN; k++) wcol[k] = W[k * D + j];
    float bj = b[j];
#pragma unroll
    for (int nn = 0; nn < 8; nn++) {
        int gi = node0 + nn;
        if (gi >= n) return;
        float s = bj;
#pragma unroll
        for (int k = 0; k < F_IN; k++) s = fmaf(xs[nn][k], wcol[k], s);
        ha[gi * D + j] = __float2half_rn(fmaxf(s, 0.0f));
    }
}

// ======================= fp16 2-term tensor-core GEMM =======================
// Chw[M,256] = A[M,256] @ Wt^T, A fp16, Wt split fp16 hi/lo: C = A*Bh + A*Bl
#define BM 128
#define BN 64
#define BK 32
#define ROWB 80u                  // 32 fp16 + 8B pad, conflict-free ldmatrix
#define SA_OFF 0u                 // A: 128 * 80 = 10240
#define B_HI  10240u              // Bh: 64 * 80 = 5120
#define B_LO  15360u              // Bl: 64 * 80 = 5120
#define STAGE_B 20480u
#define GEMM_SMEM (2 * 20480)

__global__ __launch_bounds__(256, 2) void gemm_mma(
    const __half* __restrict__ A,
    const __half* __restrict__ Bhi, const __half* __restrict__ Blo,
    float* __restrict__ Chw, int M)
{
    extern __shared__ char smem[];
    const uint32_t sb0 = smem_u32(smem);
    const int t   = threadIdx.x;
    const int wid = t >> 5, lid = t & 31;
    const int m0  = blockIdx.y * BM;
    const int n0  = blockIdx.x * BN;
    const int wm  = wid & 3;
    const int wn  = wid >> 2;

    float acc[2][4][4];
#pragma unroll
    for (int i = 0; i < 2; i++)
#pragma unroll
        for (int j = 0; j < 4; j++)
#pragma unroll
            for (int k = 0; k < 4; k++) acc[i][j][k] = 0.0f;

    const int a_r16 = lid & 15, a_kh = lid >> 4;
    const int b_n8  = lid & 7,  b_kh = (lid >> 3) & 1;

    auto issue = [&](int st, int stage) {
        const int kc = st * BK;
        const uint32_t sb = sb0 + stage * STAGE_B;
#pragma unroll
        for (int tt = t; tt < 512; tt += 256) {       // A: 128 rows x 4 chunks
            int row = tt >> 2, ch = tt & 3;
            int gr = m0 + row;
            uint32_t sz = (gr < M) ? 16u : 0u;
            int gc = (gr < M) ? gr : (M - 1);
            size_t e = (size_t)gc * 256 + kc + ch * 8;
            cp16(sb + SA_OFF + row * ROWB + ch * 16u, A + e, sz);
        }
        {                                             // B: 64 rows x 4 chunks
            int row = t >> 2, ch = t & 3;
            size_t e = (size_t)(n0 + row) * 256 + kc + ch * 8;
            uint32_t dst = sb + row * ROWB + ch * 16u;
            cp16(dst + B_HI, Bhi + e, 16u);
            cp16(dst + B_LO, Blo + e, 16u);
        }
    };

    issue(0, 0); CP_COMMIT();

#pragma unroll 1
    for (int st = 0; st < 256 / BK; st++) {
        const int cur = st & 1;
        if (st < 7) { issue(st + 1, cur ^ 1); CP_COMMIT(); CP_WAIT(1); }
        else        { CP_WAIT(0); }
        __syncthreads();

        const uint32_t sA   = sb0 + cur * STAGE_B + SA_OFF;
        const uint32_t sBhi = sb0 + cur * STAGE_B + B_HI;
        const uint32_t sBlo = sb0 + cur * STAGE_B + B_LO;

#pragma unroll
        for (int ks = 0; ks < 2; ks++) {
            const int kb = ks * 16;
            uint32_t a[2][4];
#pragma unroll
            for (int mt = 0; mt < 2; mt++) {
                uint32_t off = (uint32_t)(wm * 32 + mt * 16 + a_r16) * ROWB
                             + (uint32_t)(kb + a_kh * 8) * 2;
                ldm_x4(a[mt], sA + off);
            }
            uint32_t bh[4][2], bl[4][2];
#pragma unroll
            for (int nt = 0; nt < 4; nt++) {
                uint32_t off = (uint32_t)(wn * 32 + nt * 8 + b_n8) * ROWB
                             + (uint32_t)(kb + b_kh * 8) * 2;
                ldm_x2(bh[nt], sBhi + off);
                ldm_x2(bl[nt], sBlo + off);
            }
#pragma unroll
            for (int mt = 0; mt < 2; mt++)
#pragma unroll
                for (int nt = 0; nt < 4; nt++) {
                    mma_fp16(acc[mt][nt], a[mt], bh[nt]);
                    mma_fp16(acc[mt][nt], a[mt], bl[nt]);
                }
        }
        __syncthreads();
    }

    const int rbase = m0 + wm * 32 + (lid >> 2);
    const int cbase = n0 + wn * 32 + (lid & 3) * 2;
#pragma unroll
    for (int nt = 0; nt < 4; nt++) {
        const int col = cbase + nt * 8;
#pragma unroll
        for (int mt = 0; mt < 2; mt++) {
#pragma unroll
            for (int h = 0; h < 2; h++) {
                int row = rbase + mt * 16 + h * 8;
                if (row < M)
                    *(float2*)(Chw + (size_t)row * 256 + col) =
                        make_float2(acc[mt][nt][2 * h + 0], acc[mt][nt][2 * h + 1]);
            }
        }
    }
}

// ======================= CSR gather ==================
// node d: acc = hw[d]*dinv[d]^2 + bias + sum_{s in in(d)} hw[s]*dinv[s]*dinv[d]
// L1: writes relu -> fp16 a.  L2: writes fp32 out.
template <bool L1>
__global__ __launch_bounds__(64) void gather_k(
    const float* __restrict__ hw,
    const int* __restrict__ rowptr, const int* __restrict__ cnt,
    const int* __restrict__ csr, const float* __restrict__ dinv,
    const float* __restrict__ bias,
    float* __restrict__ outf, __half* __restrict__ ha)
{
    __shared__ int   ss[64];
    __shared__ float ws[64];
    const int d = blockIdx.x;
    const int lane = threadIdx.x;
    const float dd = dinv[d];
    const float s2 = dd * dd;

    float4 h = ((const float4*)hw)[(size_t)d * 64 + lane];
    float4 bb = ((const float4*)bias)[lane];
    float4 acc;
    acc.x = fmaf(h.x, s2, bb.x);
    acc.y = fmaf(h.y, s2, bb.y);
    acc.z = fmaf(h.z, s2, bb.z);
    acc.w = fmaf(h.w, s2, bb.w);

    const int beg = rowptr[d];
    const int c   = cnt[d];
    for (int base = 0; base < c; base += 64) {
        int m = min(64, c - base);
        __syncthreads();
        if (lane < m) {
            int s = csr[beg + base + lane];
            ss[lane] = s;
            ws[lane] = dinv[s] * dd;
        }
        __syncthreads();
#pragma unroll 4
        for (int j = 0; j < m; j++) {
            float w = ws[j];
            float4 v = ((const float4*)hw)[(size_t)ss[j] * 64 + lane];
            acc.x = fmaf(v.x, w, acc.x);
            acc.y = fmaf(v.y, w, acc.y);
            acc.z = fmaf(v.z, w, acc.z);
            acc.w = fmaf(v.w, w, acc.w);
        }
    }

    if (L1) {
        acc.x = fmaxf(acc.x, 0.f); acc.y = fmaxf(acc.y, 0.f);
        acc.z = fmaxf(acc.z, 0.f); acc.w = fmaxf(acc.w, 0.f);
        __half2 p0 = __floats2half2_rn(acc.x, acc.y);
        __half2 p1 = __floats2half2_rn(acc.z, acc.w);
        ((__half2*)ha)[(size_t)d * 128 + lane * 2 + 0] = p0;
        ((__half2*)ha)[(size_t)d * 128 + lane * 2 + 1] = p1;
    } else {
        ((float4*)outf)[(size_t)d * 64 + lane] = acc;
    }
}

// ======================= launch =======================
extern "C" void kernel_launch(void* const* d_in, const int* in_sizes, int n_in,
                              void* d_out, int out_size)
{
    const float* x  = (const float*)d_in[0];
    const int*   ei = (const int*)  d_in[1];
    const float* We = (const float*)d_in[2];
    const float* be = (const float*)d_in[3];
    const float* W1 = (const float*)d_in[4];
    const float* b1 = (const float*)d_in[5];
    const float* W2 = (const float*)d_in[6];
    const float* b2 = (const float*)d_in[7];
    float* out = (float*)d_out;

    const int N = in_sizes[0] / F_IN;       // 50000
    const int E = in_sizes[1] / 2;          // 300000
    const int* src = ei;
    const int* dst = ei + E;

    float* dinv; cudaGetSymbolAddress((void**)&dinv, g_dinv);
    float* hw;   cudaGetSymbolAddress((void**)&hw,   g_hw);
    int *cnt, *cur, *rowptr, *bsum, *csr;
    cudaGetSymbolAddress((void**)&cnt,    g_cnt);
    cudaGetSymbolAddress((void**)&cur,    g_cur);
    cudaGetSymbolAddress((void**)&rowptr, g_rowptr);
    cudaGetSymbolAddress((void**)&bsum,   g_bsum);
    cudaGetSymbolAddress((void**)&csr,    g_csr);
    __half *a, *w1hi, *w1lo, *w2hi, *w2lo;
    cudaGetSymbolAddress((void**)&a,    g_a);
    cudaGetSymbolAddress((void**)&w1hi, g_w1hi);
    cudaGetSymbolAddress((void**)&w1lo, g_w1lo);
    cudaGetSymbolAddress((void**)&w2hi, g_w2hi);
    cudaGetSymbolAddress((void**)&w2lo, g_w2lo);

    cudaFuncSetAttribute(gemm_mma, cudaFuncAttributeMaxDynamicSharedMemorySize, GEMM_SMEM);

    const int nb = (N + 255) / 256;         // 196 <= 256

    // ---- CSR build + normalization ----
    cnt_zero <<<nb, 256>>>(cnt, N);
    cnt_count<<<(E + 255) / 256, 256>>>(dst, cnt, E);
    deg_rsqrt_k<<<nb, 256>>>(cnt, dinv, N);
    scan_local<<<nb, 256>>>(cnt, rowptr, bsum, N);   // rowptr as temp exc
    scan_tops <<<1, 256>>>(bsum, nb);
    scan_add  <<<nb, 256>>>(rowptr, bsum, rowptr, cur, N);
    csr_fill  <<<(E + 255) / 256, 256>>>(src, dst, cur, csr, E);

    // ---- one-time weight split (transposed) ----
    wt_split<<<D * D / 256, 256>>>(W1, w1hi, w1lo);
    wt_split<<<D * D / 256, 256>>>(W2, w2hi, w2lo);

    // ---- embed + relu -> fp16 ----
    embed_kernel<<<(N + 7) / 8, 256>>>(x, We, be, a, N);

    dim3 gg(D / BN, (N + BM - 1) / BM);     // (4, 391)

    // layer 1: hw = a @ W1 ; gather (self+bias+edges) -> relu -> fp16 a
    gemm_mma<<<gg, 256, GEMM_SMEM>>>(a, w1hi, w1lo, hw, N);
    gather_k<true><<<N, 64>>>(hw, rowptr, cnt, csr, dinv, b1, nullptr, a);

    // layer 2: hw = a @ W2 ; gather -> out
    gemm_mma<<<gg, 256, GEMM_SMEM>>>(a, w2hi, w2lo, hw, N);
    gather_k<false><<<N, 64>>>(hw, rowptr, cnt, csr, dinv, b2, out, nullptr);
}

// round 17
// speedup vs baseline: 6.8831x; 1.2045x over previous
#include <cuda_runtime.h>
#include <cuda_fp16.h>
#include <cstdint>

#define N_NODES 50000
#define N_EDGES 300000
#define F_IN 11
#define D 256

// Scratch (bss globals, allowed per harness rules)
__device__ float g_dinv[N_NODES];
__device__ float g_hw [N_NODES * D];
// CSR by destination
__device__ int g_cnt   [N_NODES];
__device__ int g_cur   [N_NODES];
__device__ int g_rowptr[N_NODES];
__device__ int g_bsum  [256];
__device__ int g_csr   [N_EDGES];
// fp16 activation buffer (h0 for layer1, relu(agg1) for layer2)
__device__ __half g_a[N_NODES * D];
// transposed fp16 weights: Wt[n][k] = W[k][n]
__device__ __half g_w1t[D * D];
__device__ __half g_w2t[D * D];

// ======================= helpers =======================
__device__ __forceinline__ uint32_t smem_u32(const void* p) {
    uint32_t a;
    asm("{ .reg .u64 t; cvta.to.shared.u64 t, %1; cvt.u32.u64 %0, t; }" : "=r"(a) : "l"(p));
    return a;
}
__device__ __forceinline__ void ldm_x4(uint32_t* r, uint32_t addr) {
    asm volatile("ldmatrix.sync.aligned.m8n8.x4.shared.b16 {%0,%1,%2,%3}, [%4];"
                 : "=r"(r[0]), "=r"(r[1]), "=r"(r[2]), "=r"(r[3]) : "r"(addr));
}
__device__ __forceinline__ void ldm_x2(uint32_t* r, uint32_t addr) {
    asm volatile("ldmatrix.sync.aligned.m8n8.x2.shared.b16 {%0,%1}, [%2];"
                 : "=r"(r[0]), "=r"(r[1]) : "r"(addr));
}
__device__ __forceinline__ void mma_fp16(float* c, const uint32_t* a, const uint32_t* b) {
    asm volatile("mma.sync.aligned.m16n8k16.row.col.f32.f16.f16.f32 "
                 "{%0,%1,%2,%3}, {%4,%5,%6,%7}, {%8,%9}, {%0,%1,%2,%3};"
                 : "+f"(c[0]), "+f"(c[1]), "+f"(c[2]), "+f"(c[3])
                 : "r"(a[0]), "r"(a[1]), "r"(a[2]), "r"(a[3]), "r"(b[0]), "r"(b[1]));
}
__device__ __forceinline__ void cp16(uint32_t dst, const __half* src, uint32_t sz) {
    uint64_t g;
    asm("cvta.to.global.u64 %0, %1;" : "=l"(g) : "l"(src));
    asm volatile("cp.async.cg.shared.global [%0], [%1], 16, %2;"
                 :: "r"(dst), "l"(g), "r"(sz) : "memory");
}
#define CP_COMMIT() asm volatile("cp.async.commit_group;" ::: "memory")
#define CP_WAIT(n)  asm volatile("cp.async.wait_group %0;" :: "n"(n) : "memory")

// ======================= CSR build =======================
__global__ void cnt_zero(int* cnt, int n) {
    int i = blockIdx.x * blockDim.x + threadIdx.x;
    if (i < n) cnt[i] = 0;
}
__global__ void cnt_count(const int* __restrict__ dst, int* cnt, int e) {
    int i = blockIdx.x * blockDim.x + threadIdx.x;
    if (i < e) atomicAdd(&cnt[dst[i]], 1);
}
// local exclusive scan + per-block sum + dinv = rsqrt(cnt+1) fused
__global__ void scan_local(const int* __restrict__ cnt, int* exc, int* bsum,
                           float* __restrict__ dinv, int n) {
    __shared__ int s[256];
    int i = blockIdx.x * 256 + threadIdx.x;
    int v = (i < n) ? cnt[i] : 0;
    if (i < n) dinv[i] = rsqrtf((float)(v + 1));   // +1 self-loop
    s[threadIdx.x] = v;
    __syncthreads();
#pragma unroll
    for (int d2 = 1; d2 < 256; d2 <<= 1) {
        int t = (threadIdx.x >= d2) ? s[threadIdx.x - d2] : 0;
        __syncthreads();
        s[threadIdx.x] += t;
        __syncthreads();
    }
    if (i < n) exc[i] = s[threadIdx.x] - v;
    if (threadIdx.x == 255) bsum[blockIdx.x] = s[255];
}
__global__ void scan_tops(int* bsum, int nb) {   // single block, nb <= 256
    __shared__ int s[256];
    int v = (threadIdx.x < nb) ? bsum[threadIdx.x] : 0;
    s[threadIdx.x] = v;
    __syncthreads();
#pragma unroll
    for (int d2 = 1; d2 < 256; d2 <<= 1) {
        int t = (threadIdx.x >= d2) ? s[threadIdx.x - d2] : 0;
        __syncthreads();
        s[threadIdx.x] += t;
        __syncthreads();
    }
    if (threadIdx.x < nb) bsum[threadIdx.x] = s[threadIdx.x] - v;   // exclusive
}
__global__ void scan_add(const int* __restrict__ exc, const int* __restrict__ bsum,
                         int* rowptr, int* cur, int n) {
    int i = blockIdx.x * 256 + threadIdx.x;
    if (i < n) {
        int off = exc[i] + bsum[blockIdx.x];
        rowptr[i] = off;
        cur[i] = off;
    }
}
__global__ void csr_fill(const int* __restrict__ src, const int* __restrict__ dst,
                         int* cur, int* csr, int e) {
    int i = blockIdx.x * blockDim.x + threadIdx.x;
    if (i < e) {
        int slot = atomicAdd(&cur[dst[i]], 1);
        csr[slot] = src[i];
    }
}

// ======================= weight convert (both, transposed, one-time) ==========
__global__ __launch_bounds__(256) void wt_convert(
    const float* __restrict__ W1, const float* __restrict__ W2,
    __half* __restrict__ W1t, __half* __restrict__ W2t)
{
    int bid = blockIdx.x;
    const float* W = (bid < 256) ? W1 : W2;
    __half* Wt     = (bid < 256) ? W1t : W2t;
    int idx = (bid & 255) * 256 + threadIdx.x;  // 65536 per matrix
    int k = idx >> 8, n = idx & 255;
    Wt[n * 256 + k] = __float2half_rn(W[k * 256 + n]);
}

// ======================= embed: fp16 of relu(x @ We + be) =======================
__global__ __launch_bounds__(256) void embed_kernel(
    const float* __restrict__ x, const float* __restrict__ W,
    const float* __restrict__ b, __half* __restrict__ ha, int n)
{
    __shared__ float xs[8][F_IN];
    int j = threadIdx.x;
    int node0 = blockIdx.x * 8;
    int t = threadIdx.x;
    if (t < 8 * F_IN) {
        int nn = t / F_IN, kk = t % F_IN;
        int gi = node0 + nn;
        xs[nn][kk] = (gi < n) ? x[gi * F_IN + kk] : 0.0f;
    }
    __syncthreads();
    float wcol[F_IN];
#pragma unroll
    for (int k = 0; k < F_IN; k++) wcol[k] = W[k * D + j];
    float bj = b[j];
#pragma unroll
    for (int nn = 0; nn < 8; nn++) {
        int gi = node0 + nn;
        if (gi >= n) return;
        float s = bj;
#pragma unroll
        for (int k = 0; k < F_IN; k++) s = fmaf(xs[nn][k], wcol[k], s);
        ha[gi * D + j] = __float2half_rn(fmaxf(s, 0.0f));
    }
}

// ======================= fp16 tensor-core GEMM (1-term) =======================
// Chw[M,256] = A[M,256] @ Wt^T, both fp16, fp32 accumulate.
#define BM 128
#define BN 64
#define BK 32
#define ROWB 80u                  // 32 fp16 + 8B pad, conflict-free ldmatrix
#define SA_OFF 0u                 // A: 128 * 80 = 10240
#define SB_OFF 10240u             // B: 64 * 80 = 5120
#define STAGE_B 15360u
#define GEMM_SMEM (2 * 15360)

__global__ __launch_bounds__(256, 2) void gemm_mma(
    const __half* __restrict__ A, const __half* __restrict__ B,
    float* __restrict__ Chw, int M)
{
    extern __shared__ char smem[];
    const uint32_t sb0 = smem_u32(smem);
    const int t   = threadIdx.x;
    const int wid = t >> 5, lid = t & 31;
    const int m0  = blockIdx.y * BM;
    const int n0  = blockIdx.x * BN;
    const int wm  = wid & 3;
    const int wn  = wid >> 2;

    float acc[2][4][4];
#pragma unroll
    for (int i = 0; i < 2; i++)
#pragma unroll
        for (int j = 0; j < 4; j++)
#pragma unroll
            for (int k = 0; k < 4; k++) acc[i][j][k] = 0.0f;

    const int a_r16 = lid & 15, a_kh = lid >> 4;
    const int b_n8  = lid & 7,  b_kh = (lid >> 3) & 1;

    auto issue = [&](int st, int stage) {
        const int kc = st * BK;
        const uint32_t sb = sb0 + stage * STAGE_B;
#pragma unroll
        for (int tt = t; tt < 512; tt += 256) {       // A: 128 rows x 4 chunks
            int row = tt >> 2, ch = tt & 3;
            int gr = m0 + row;
            uint32_t sz = (gr < M) ? 16u : 0u;
            int gc = (gr < M) ? gr : (M - 1);
            size_t e = (size_t)gc * 256 + kc + ch * 8;
            cp16(sb + SA_OFF + row * ROWB + ch * 16u, A + e, sz);
        }
        {                                             // B: 64 rows x 4 chunks
            int row = t >> 2, ch = t & 3;
            size_t e = (size_t)(n0 + row) * 256 + kc + ch * 8;
            cp16(sb + SB_OFF + row * ROWB + ch * 16u, B + e, 16u);
        }
    };

    issue(0, 0); CP_COMMIT();

#pragma unroll 1
    for (int st = 0; st < 256 / BK; st++) {
        const int cur = st & 1;
        if (st < 7) { issue(st + 1, cur ^ 1); CP_COMMIT(); CP_WAIT(1); }
        else        { CP_WAIT(0); }
        __syncthreads();

        const uint32_t sA = sb0 + cur * STAGE_B + SA_OFF;
        const uint32_t sB = sb0 + cur * STAGE_B + SB_OFF;

#pragma unroll
        for (int ks = 0; ks < 2; ks++) {
            const int kb = ks * 16;
            uint32_t a[2][4];
#pragma unroll
            for (int mt = 0; mt < 2; mt++) {
                uint32_t off = (uint32_t)(wm * 32 + mt * 16 + a_r16) * ROWB
                             + (uint32_t)(kb + a_kh * 8) * 2;
                ldm_x4(a[mt], sA + off);
            }
            uint32_t b[4][2];
#pragma unroll
            for (int nt = 0; nt < 4; nt++) {
                uint32_t off = (uint32_t)(wn * 32 + nt * 8 + b_n8) * ROWB
                             + (uint32_t)(kb + b_kh * 8) * 2;
                ldm_x2(b[nt], sB + off);
            }
#pragma unroll
            for (int mt = 0; mt < 2; mt++)
#pragma unroll
                for (int nt = 0; nt < 4; nt++)
                    mma_fp16(acc[mt][nt], a[mt], b[nt]);
        }
        __syncthreads();
    }

    const int rbase = m0 + wm * 32 + (lid >> 2);
    const int cbase = n0 + wn * 32 + (lid & 3) * 2;
#pragma unroll
    for (int nt = 0; nt < 4; nt++) {
        const int col = cbase + nt * 8;
#pragma unroll
        for (int mt = 0; mt < 2; mt++) {
#pragma unroll
            for (int h = 0; h < 2; h++) {
                int row = rbase + mt * 16 + h * 8;
                if (row < M)
                    *(float2*)(Chw + (size_t)row * 256 + col) =
                        make_float2(acc[mt][nt][2 * h + 0], acc[mt][nt][2 * h + 1]);
            }
        }
    }
}

// ======================= CSR gather ==================
// node d: acc = hw[d]*dinv[d]^2 + bias + sum_{s in in(d)} hw[s]*dinv[s]*dinv[d]
// L1: writes relu -> fp16 a.  L2: writes fp32 out.
template <bool L1>
__global__ __launch_bounds__(64) void gather_k(
    const float* __restrict__ hw,
    const int* __restrict__ rowptr, const int* __restrict__ cnt,
    const int* __restrict__ csr, const float* __restrict__ dinv,
    const float* __restrict__ bias,
    float* __restrict__ outf, __half* __restrict__ ha)
{
    __shared__ int   ss[64];
    __shared__ float ws[64];
    const int d = blockIdx.x;
    const int lane = threadIdx.x;
    const float dd = dinv[d];
    const float s2 = dd * dd;

    float4 h = ((const float4*)hw)[(size_t)d * 64 + lane];
    float4 bb = ((const float4*)bias)[lane];
    float4 acc;
    acc.x = fmaf(h.x, s2, bb.x);
    acc.y = fmaf(h.y, s2, bb.y);
    acc.z = fmaf(h.z, s2, bb.z);
    acc.w = fmaf(h.w, s2, bb.w);

    const int beg = rowptr[d];
    const int c   = cnt[d];
    for (int base = 0; base < c; base += 64) {
        int m = min(64, c - base);
        __syncthreads();
        if (lane < m) {
            int s = csr[beg + base + lane];
            ss[lane] = s;
            ws[lane] = dinv[s] * dd;
        }
        __syncthreads();
#pragma unroll 4
        for (int j = 0; j < m; j++) {
            float w = ws[j];
            float4 v = ((const float4*)hw)[(size_t)ss[j] * 64 + lane];
            acc.x = fmaf(v.x, w, acc.x);
            acc.y = fmaf(v.y, w, acc.y);
            acc.z = fmaf(v.z, w, acc.z);
            acc.w = fmaf(v.w, w, acc.w);
        }
    }

    if (L1) {
        acc.x = fmaxf(acc.x, 0.f); acc.y = fmaxf(acc.y, 0.f);
        acc.z = fmaxf(acc.z, 0.f); acc.w = fmaxf(acc.w, 0.f);
        __half2 p0 = __floats2half2_rn(acc.x, acc.y);
        __half2 p1 = __floats2half2_rn(acc.z, acc.w);
        ((__half2*)ha)[(size_t)d * 128 + lane * 2 + 0] = p0;
        ((__half2*)ha)[(size_t)d * 128 + lane * 2 + 1] = p1;
    } else {
        ((float4*)outf)[(size_t)d * 64 + lane] = acc;
    }
}

// ======================= launch =======================
extern "C" void kernel_launch(void* const* d_in, const int* in_sizes, int n_in,
                              void* d_out, int out_size)
{
    const float* x  = (const float*)d_in[0];
    const int*   ei = (const int*)  d_in[1];
    const float* We = (const float*)d_in[2];
    const float* be = (const float*)d_in[3];
    const float* W1 = (const float*)d_in[4];
    const float* b1 = (const float*)d_in[5];
    const float* W2 = (const float*)d_in[6];
    const float* b2 = (const float*)d_in[7];
    float* out = (float*)d_out;

    const int N = in_sizes[0] / F_IN;       // 50000
    const int E = in_sizes[1] / 2;          // 300000
    const int* src = ei;
    const int* dst = ei + E;

    float* dinv; cudaGetSymbolAddress((void**)&dinv, g_dinv);
    float* hw;   cudaGetSymbolAddress((void**)&hw,   g_hw);
    int *cnt, *cur, *rowptr, *bsum, *csr;
    cudaGetSymbolAddress((void**)&cnt,    g_cnt);
    cudaGetSymbolAddress((void**)&cur,    g_cur);
    cudaGetSymbolAddress((void**)&rowptr, g_rowptr);
    cudaGetSymbolAddress((void**)&bsum,   g_bsum);
    cudaGetSymbolAddress((void**)&csr,    g_csr);
    __half *a, *w1t, *w2t;
    cudaGetSymbolAddress((void**)&a,   g_a);
    cudaGetSymbolAddress((void**)&w1t, g_w1t);
    cudaGetSymbolAddress((void**)&w2t, g_w2t);

    cudaFuncSetAttribute(gemm_mma, cudaFuncAttributeMaxDynamicSharedMemorySize, GEMM_SMEM);

    const int nb = (N + 255) / 256;         // 196 <= 256

    // ---- CSR build + normalization ----
    cnt_zero <<<nb, 256>>>(cnt, N);
    cnt_count<<<(E + 255) / 256, 256>>>(dst, cnt, E);
    scan_local<<<nb, 256>>>(cnt, rowptr, bsum, dinv, N);   // rowptr as temp exc
    scan_tops <<<1, 256>>>(bsum, nb);
    scan_add  <<<nb, 256>>>(rowptr, bsum, rowptr, cur, N);
    csr_fill  <<<(E + 255) / 256, 256>>>(src, dst, cur, csr, E);

    // ---- one-time weight convert (both, transposed) ----
    wt_convert<<<512, 256>>>(W1, W2, w1t, w2t);

    // ---- embed + relu -> fp16 ----
    embed_kernel<<<(N + 7) / 8, 256>>>(x, We, be, a, N);

    dim3 gg(D / BN, (N + BM - 1) / BM);     // (4, 391)

    // layer 1: hw = a @ W1 ; gather (self+bias+edges) -> relu -> fp16 a
    gemm_mma<<<gg, 256, GEMM_SMEM>>>(a, w1t, hw, N);
    gather_k<true><<<N, 64>>>(hw, rowptr, cnt, csr, dinv, b1, nullptr, a);

    // layer 2: hw = a @ W2 ; gather -> out
    gemm_mma<<<gg, 256, GEMM_SMEM>>>(a, w2t, hw, N);
    gather_k<false><<<N, 64>>>(hw, rowptr, cnt, csr, dinv, b2, out, nullptr);
}